// round 1
// baseline (speedup 1.0000x reference)
#include <cuda_runtime.h>
#include <math.h>

// Problem constants
#define Bc 2
#define Tc 2048
#define Ec 2048
#define Hc 16
#define Dc 64
#define MTOT (Bc * Tc)  // 4096

// ---------------------------------------------------------------------------
// Device scratch (no allocations allowed)
// ---------------------------------------------------------------------------
__device__ float g_Q[Bc * Tc * Ec];                       // [B*T, 2048] (pre-scaled by D^-0.5)
__device__ float g_K[Bc * Tc * Ec];                       // [B*T, 2048]
__device__ float g_V[Bc * Tc * Ec];                       // [B*T, 2048]
__device__ float g_O[(size_t)Bc * 2 * Hc * Tc * 2 * Dc];  // [B, 2H, T, 128]
__device__ float g_ctx[Bc * Tc * Ec];                     // [B*T, 2048]
__device__ float g_lam;

// ---------------------------------------------------------------------------
// SGEMM: C[m,n] = alpha * sum_k X[m,k] * W[n,k]   (i.e. X @ W^T)
// BM=BN=128, BK=8, 256 threads, 8x8 per-thread microtile, global prefetch.
// M,N,K assumed multiples of 128/128/8.
// ---------------------------------------------------------------------------
__global__ __launch_bounds__(256) void sgemm_xwT(
    const float* __restrict__ X, const float* __restrict__ W,
    float* __restrict__ C, int M, int N, int K, float alpha)
{
    __shared__ float As[8][128];
    __shared__ float Bs[8][128];

    const int m0 = blockIdx.y * 128;
    const int n0 = blockIdx.x * 128;
    const int tid = threadIdx.x;
    const int tm = tid >> 4;        // 0..15
    const int tn = tid & 15;        // 0..15
    const int lrow = tid >> 1;      // 0..127
    const int lh = (tid & 1) * 4;   // 0 or 4

    const float* Xp = X + (size_t)(m0 + lrow) * K + lh;
    const float* Wp = W + (size_t)(n0 + lrow) * K + lh;

    float acc[8][8];
#pragma unroll
    for (int i = 0; i < 8; i++)
#pragma unroll
        for (int j = 0; j < 8; j++) acc[i][j] = 0.f;

    float4 xa = *(const float4*)(Xp);
    float4 wa = *(const float4*)(Wp);

    for (int k0 = 0; k0 < K; k0 += 8) {
        As[lh + 0][lrow] = xa.x; As[lh + 1][lrow] = xa.y;
        As[lh + 2][lrow] = xa.z; As[lh + 3][lrow] = xa.w;
        Bs[lh + 0][lrow] = wa.x; Bs[lh + 1][lrow] = wa.y;
        Bs[lh + 2][lrow] = wa.z; Bs[lh + 3][lrow] = wa.w;
        __syncthreads();

        // prefetch next tile while computing on this one
        if (k0 + 8 < K) {
            xa = *(const float4*)(Xp + k0 + 8);
            wa = *(const float4*)(Wp + k0 + 8);
        }

#pragma unroll
        for (int k = 0; k < 8; k++) {
            float ra[8], rb[8];
            *(float4*)&ra[0] = *(const float4*)&As[k][tm * 8];
            *(float4*)&ra[4] = *(const float4*)&As[k][tm * 8 + 4];
            *(float4*)&rb[0] = *(const float4*)&Bs[k][tn * 8];
            *(float4*)&rb[4] = *(const float4*)&Bs[k][tn * 8 + 4];
#pragma unroll
            for (int i = 0; i < 8; i++)
#pragma unroll
                for (int j = 0; j < 8; j++)
                    acc[i][j] = fmaf(ra[i], rb[j], acc[i][j]);
        }
        __syncthreads();
    }

#pragma unroll
    for (int i = 0; i < 8; i++) {
        float* Cp = C + (size_t)(m0 + tm * 8 + i) * N + n0 + tn * 8;
        float4 o0, o1;
        o0.x = acc[i][0] * alpha; o0.y = acc[i][1] * alpha;
        o0.z = acc[i][2] * alpha; o0.w = acc[i][3] * alpha;
        o1.x = acc[i][4] * alpha; o1.y = acc[i][5] * alpha;
        o1.z = acc[i][6] * alpha; o1.w = acc[i][7] * alpha;
        *(float4*)(Cp) = o0;
        *(float4*)(Cp + 4) = o1;
    }
}

// ---------------------------------------------------------------------------
// Lambda scalar: lam = exp(sum lq1*lk1) - exp(sum lq2*lk2) + LAMBDA_INIT
// ---------------------------------------------------------------------------
__global__ void lambda_kernel(const float* __restrict__ lq1, const float* __restrict__ lk1,
                              const float* __restrict__ lq2, const float* __restrict__ lk2)
{
    float s1 = 0.f, s2 = 0.f;
    for (int i = 0; i < Dc; i++) {
        s1 += lq1[i] * lk1[i];
        s2 += lq2[i] * lk2[i];
    }
    const float LI = 0.8f - 0.6f * expf(-3.6f);
    g_lam = expf(s1) - expf(s2) + LI;
}

// ---------------------------------------------------------------------------
// Causal flash attention (fp32, online softmax).
// Grid: (T/64, 2H, B). Block: 256 threads.
// Q layout: [B*T, 2048] cols h2*64+d (pre-scaled). K same. V cols (h2/2)*128+e.
// O out: [B, 2H, T, 128].
// smem: Qs[d][m] 16KB, Ks[d][n] 16KB, Ss[n][m] 16KB, Vs[n][e] 32KB = 80KB.
// ---------------------------------------------------------------------------
__global__ __launch_bounds__(256) void flash_kernel(
    const float* __restrict__ Q, const float* __restrict__ Km,
    const float* __restrict__ Vm, float* __restrict__ O)
{
    extern __shared__ float sm[];
    float* Qs = sm;           // 4096: [64 d][64 m]
    float* Ks = sm + 4096;    // 4096: [64 d][64 n]
    float* Ss = sm + 8192;    // 4096: [64 n][64 m]
    float* Vs = sm + 12288;   // 8192: [64 n][128 e]

    const int qtile = blockIdx.x;
    const int h2 = blockIdx.y;
    const int b = blockIdx.z;
    const int tid = threadIdx.x;
    const int tm = tid >> 4;   // 0..15 -> rows tm*4..tm*4+3
    const int tn = tid & 15;   // 0..15 -> score cols tn*4.. / out cols tn*8..
    const int qm0 = qtile * 64;
    const int qoff = h2 * 64;
    const int voff = (h2 >> 1) * 128;

    // load Q tile (d-major)
    {
        const int m = tid >> 2, q4 = tid & 3;
        const float* Qrow = Q + (size_t)(b * Tc + qm0 + m) * Ec + qoff;
#pragma unroll
        for (int j = 0; j < 4; j++) {
            const int f = q4 + 4 * j;
            float4 v = *(const float4*)(Qrow + f * 4);
            Qs[(f * 4 + 0) * 64 + m] = v.x;
            Qs[(f * 4 + 1) * 64 + m] = v.y;
            Qs[(f * 4 + 2) * 64 + m] = v.z;
            Qs[(f * 4 + 3) * 64 + m] = v.w;
        }
    }

    float acc[4][8];
#pragma unroll
    for (int i = 0; i < 4; i++)
#pragma unroll
        for (int j = 0; j < 8; j++) acc[i][j] = 0.f;
    float mrow[4] = {-1e30f, -1e30f, -1e30f, -1e30f};
    float lrow[4] = {0.f, 0.f, 0.f, 0.f};

    for (int kt = 0; kt <= qtile; kt++) {
        __syncthreads();  // prev iter readers done (also covers Q load on iter 0)

        // load K and V tiles
        {
            const int n = tid >> 2, q4 = tid & 3;
            const float* Krow = Km + (size_t)(b * Tc + kt * 64 + n) * Ec + qoff;
#pragma unroll
            for (int j = 0; j < 4; j++) {
                const int f = q4 + 4 * j;
                float4 v = *(const float4*)(Krow + f * 4);
                Ks[(f * 4 + 0) * 64 + n] = v.x;
                Ks[(f * 4 + 1) * 64 + n] = v.y;
                Ks[(f * 4 + 2) * 64 + n] = v.z;
                Ks[(f * 4 + 3) * 64 + n] = v.w;
            }
            const float* Vrow = Vm + (size_t)(b * Tc + kt * 64 + n) * Ec + voff;
#pragma unroll
            for (int j = 0; j < 8; j++) {
                const int f = q4 + 4 * j;
                *(float4*)(Vs + n * 128 + f * 4) = *(const float4*)(Vrow + f * 4);
            }
        }
        __syncthreads();

        // S = Q @ K^T  (4x4 per thread)
        float s[4][4];
#pragma unroll
        for (int i = 0; i < 4; i++)
#pragma unroll
            for (int j = 0; j < 4; j++) s[i][j] = 0.f;
#pragma unroll 8
        for (int d = 0; d < 64; d++) {
            float4 a = *(const float4*)(Qs + d * 64 + tm * 4);
            float4 kk = *(const float4*)(Ks + d * 64 + tn * 4);
            float ra[4] = {a.x, a.y, a.z, a.w};
            float rk[4] = {kk.x, kk.y, kk.z, kk.w};
#pragma unroll
            for (int i = 0; i < 4; i++)
#pragma unroll
                for (int j = 0; j < 4; j++)
                    s[i][j] = fmaf(ra[i], rk[j], s[i][j]);
        }

        // causal mask (only the diagonal tile: kt*64 == qm0)
        if (kt == qtile) {
#pragma unroll
            for (int i = 0; i < 4; i++)
#pragma unroll
                for (int j = 0; j < 4; j++)
                    if (tn * 4 + j > tm * 4 + i) s[i][j] = -1e30f;
        }

        // online softmax per row (row group = 16 consecutive lanes)
#pragma unroll
        for (int i = 0; i < 4; i++) {
            float tmax = fmaxf(fmaxf(s[i][0], s[i][1]), fmaxf(s[i][2], s[i][3]));
#pragma unroll
            for (int off = 8; off > 0; off >>= 1)
                tmax = fmaxf(tmax, __shfl_xor_sync(0xffffffffu, tmax, off, 16));
            const float mnew = fmaxf(mrow[i], tmax);
            const float al = __expf(mrow[i] - mnew);
            float tsum = 0.f;
#pragma unroll
            for (int j = 0; j < 4; j++) {
                const float p = __expf(s[i][j] - mnew);
                s[i][j] = p;
                tsum += p;
            }
#pragma unroll
            for (int off = 8; off > 0; off >>= 1)
                tsum += __shfl_xor_sync(0xffffffffu, tsum, off, 16);
            lrow[i] = lrow[i] * al + tsum;
            mrow[i] = mnew;
#pragma unroll
            for (int j = 0; j < 8; j++) acc[i][j] *= al;
#pragma unroll
            for (int j = 0; j < 4; j++)
                Ss[(tn * 4 + j) * 64 + tm * 4 + i] = s[i][j];
        }
        __syncthreads();

        // O += P @ V  (rows tm*4.., cols tn*8..)
#pragma unroll 4
        for (int n = 0; n < 64; n++) {
            float4 p4 = *(const float4*)(Ss + n * 64 + tm * 4);
            float4 v0 = *(const float4*)(Vs + n * 128 + tn * 8);
            float4 v1 = *(const float4*)(Vs + n * 128 + tn * 8 + 4);
            float pv[4] = {p4.x, p4.y, p4.z, p4.w};
            float vv[8] = {v0.x, v0.y, v0.z, v0.w, v1.x, v1.y, v1.z, v1.w};
#pragma unroll
            for (int i = 0; i < 4; i++)
#pragma unroll
                for (int j = 0; j < 8; j++)
                    acc[i][j] = fmaf(pv[i], vv[j], acc[i][j]);
        }
    }

    // epilogue: divide by l, store
#pragma unroll
    for (int i = 0; i < 4; i++) {
        const float inv = 1.f / lrow[i];
        float* dst = O + ((size_t)(b * 2 * Hc + h2) * Tc + qm0 + tm * 4 + i) * 128 + tn * 8;
        float4 o0, o1;
        o0.x = acc[i][0] * inv; o0.y = acc[i][1] * inv;
        o0.z = acc[i][2] * inv; o0.w = acc[i][3] * inv;
        o1.x = acc[i][4] * inv; o1.y = acc[i][5] * inv;
        o1.z = acc[i][6] * inv; o1.w = acc[i][7] * inv;
        *(float4*)(dst) = o0;
        *(float4*)(dst + 4) = o1;
    }
}

// ---------------------------------------------------------------------------
// Combine: x = O[2h] - lam*O[2h+1]; RMSNorm over 128; * g * (1-LI)
// Grid: B*H*T blocks of 128 threads. ctx layout [B*T, H*128].
// ---------------------------------------------------------------------------
__global__ __launch_bounds__(128) void combine_kernel(
    const float* __restrict__ O, const float* __restrict__ g,
    float* __restrict__ ctx)
{
    const int idx = blockIdx.x;            // (b*H + h)*T + t
    const int t = idx % Tc;
    const int h = (idx / Tc) % Hc;
    const int b = idx / (Tc * Hc);
    const int e = threadIdx.x;

    const size_t base1 = ((size_t)(b * 2 * Hc + 2 * h) * Tc + t) * 128;
    const size_t base2 = base1 + (size_t)Tc * 128;

    const float lam = g_lam;
    const float x = O[base1 + e] - lam * O[base2 + e];

    float v = x * x;
#pragma unroll
    for (int off = 16; off > 0; off >>= 1)
        v += __shfl_xor_sync(0xffffffffu, v, off, 32);

    __shared__ float red[4];
    if ((threadIdx.x & 31) == 0) red[threadIdx.x >> 5] = v;
    __syncthreads();
    const float tot = red[0] + red[1] + red[2] + red[3];
    const float rms = rsqrtf(tot * (1.f / 128.f) + 1e-5f);

    const float LI = 0.8f - 0.6f * expf(-3.6f);
    ctx[(size_t)(b * Tc + t) * Ec + h * 128 + e] = x * rms * g[e] * (1.f - LI);
}

// ---------------------------------------------------------------------------
// Host launcher
// ---------------------------------------------------------------------------
extern "C" void kernel_launch(void* const* d_in, const int* in_sizes, int n_in,
                              void* d_out, int out_size)
{
    (void)in_sizes; (void)n_in; (void)out_size;

    const float* query = (const float*)d_in[0];
    const float* Wq = (const float*)d_in[1];
    const float* Wk = (const float*)d_in[2];
    const float* Wv = (const float*)d_in[3];
    const float* Wo = (const float*)d_in[4];
    const float* lq1 = (const float*)d_in[5];
    const float* lk1 = (const float*)d_in[6];
    const float* lq2 = (const float*)d_in[7];
    const float* lk2 = (const float*)d_in[8];
    const float* gw = (const float*)d_in[9];
    float* out = (float*)d_out;

    float *pQ, *pK, *pV, *pO, *pC;
    cudaGetSymbolAddress((void**)&pQ, g_Q);
    cudaGetSymbolAddress((void**)&pK, g_K);
    cudaGetSymbolAddress((void**)&pV, g_V);
    cudaGetSymbolAddress((void**)&pO, g_O);
    cudaGetSymbolAddress((void**)&pC, g_ctx);

    const dim3 ggrid(Ec / 128, MTOT / 128);

    // projections (Q pre-scaled by D^-0.5 = 0.125)
    sgemm_xwT<<<ggrid, 256>>>(query, Wq, pQ, MTOT, Ec, Ec, 0.125f);
    sgemm_xwT<<<ggrid, 256>>>(query, Wk, pK, MTOT, Ec, Ec, 1.0f);
    sgemm_xwT<<<ggrid, 256>>>(query, Wv, pV, MTOT, Ec, Ec, 1.0f);

    lambda_kernel<<<1, 1>>>(lq1, lk1, lq2, lk2);

    const int FLASH_SMEM = 81920;
    cudaFuncSetAttribute(flash_kernel, cudaFuncAttributeMaxDynamicSharedMemorySize, FLASH_SMEM);
    flash_kernel<<<dim3(Tc / 64, 2 * Hc, Bc), 256, FLASH_SMEM>>>(pQ, pK, pV, pO);

    combine_kernel<<<Bc * Hc * Tc, 128>>>(pO, gw, pC);

    // output projection
    sgemm_xwT<<<ggrid, 256>>>(pC, Wo, out, MTOT, Ec, Ec, 1.0f);
}

// round 3
// speedup vs baseline: 1.6695x; 1.6695x over previous
#include <cuda_runtime.h>
#include <cstdint>
#include <math.h>

// Problem constants
#define Bc 2
#define Tc 2048
#define Ec 2048
#define Hc 16
#define Dc 64
#define MTOT (Bc * Tc)  // 4096

// ---------------------------------------------------------------------------
// Device scratch (no allocations allowed)
// ---------------------------------------------------------------------------
__device__ float g_Q[Bc * Tc * Ec];                       // [B*T, 2048] (pre-scaled)
__device__ float g_K[Bc * Tc * Ec];                       // [B*T, 2048]
__device__ float g_V[Bc * Tc * Ec];                       // [B*T, 2048]
__device__ float g_O[(size_t)Bc * 2 * Hc * Tc * 2 * Dc];  // [B, 2H, T, 128]
__device__ float g_ctx[Bc * Tc * Ec];                     // [B*T, 2048]
__device__ float g_lam;

// ---------------------------------------------------------------------------
// PTX helpers
// ---------------------------------------------------------------------------
__device__ __forceinline__ uint32_t smem_u32(const void* p) {
    uint32_t a;
    asm("{ .reg .u64 t; cvta.to.shared.u64 t, %1; cvt.u32.u64 %0, t; }" : "=r"(a) : "l"(p));
    return a;
}
__device__ __forceinline__ void cpa16(uint32_t saddr, const void* g) {
    asm volatile("cp.async.cg.shared.global [%0], [%1], 16;" :: "r"(saddr), "l"(g));
}
#define CP_COMMIT() asm volatile("cp.async.commit_group;" ::: "memory")
#define CP_WAIT(n) asm volatile("cp.async.wait_group %0;" :: "n"(n) : "memory")

__device__ __forceinline__ uint32_t cvt_tf32(float f) {
    uint32_t r;
    asm("cvt.rna.tf32.f32 %0, %1;" : "=r"(r) : "f"(f));
    return r;
}
__device__ __forceinline__ void mma_tf32(float* d, const uint32_t* a, const uint32_t* b) {
    asm volatile(
        "mma.sync.aligned.m16n8k8.row.col.f32.tf32.tf32.f32 "
        "{%0,%1,%2,%3}, {%4,%5,%6,%7}, {%8,%9}, {%0,%1,%2,%3};"
        : "+f"(d[0]), "+f"(d[1]), "+f"(d[2]), "+f"(d[3])
        : "r"(a[0]), "r"(a[1]), "r"(a[2]), "r"(a[3]), "r"(b[0]), "r"(b[1]));
}

// ---------------------------------------------------------------------------
// TF32 tensor-core GEMM: C[m,n] = alpha * sum_k X[m,k] * W[n,k]  (X @ W^T)
// CTA 128x128, BK=32, 8 warps (2x4), warp tile 64x32, m16n8k8 atoms.
// smem: padded stride 36 floats (conflict-free fragment loads).
// ---------------------------------------------------------------------------
#define BM 128
#define BN 128
#define BK 32
#define LDA 36
#define STAGE_FLOATS (BM * LDA)                 // 4608 floats per matrix
#define GSMEM_BYTES (4 * STAGE_FLOATS * 4)      // 2 stages x (A+B) = 73728 B

__global__ __launch_bounds__(256) void gemm_tf32mma(
    const float* __restrict__ X, const float* __restrict__ W,
    float* __restrict__ C, int M, int N, int K, float alpha)
{
    extern __shared__ __align__(16) float smem[];
    const int tid = threadIdx.x;
    const int wid = tid >> 5;
    const int lane = tid & 31;
    const int g = lane >> 2;     // 0..7
    const int tig = lane & 3;    // 0..3
    const int warp_m = (wid & 1) * 64;
    const int warp_n = (wid >> 1) * 32;
    const int m0 = blockIdx.y * BM;
    const int n0 = blockIdx.x * BN;
    const int NK = K / BK;

    float acc[4][4][4];
#pragma unroll
    for (int i = 0; i < 4; i++)
#pragma unroll
        for (int j = 0; j < 4; j++)
#pragma unroll
            for (int r = 0; r < 4; r++) acc[i][j][r] = 0.f;

    // --- async stage loader: A tile [128 x 32] + B tile [128 x 32], stride 36
    const int lrow = tid >> 3;        // 0..31 (x4 iters -> 128 rows? no: c>>3)
    (void)lrow;

    // prologue: stage 0 <- kt 0
    {
        float* Ad = smem;
        float* Bd = smem + STAGE_FLOATS;
#pragma unroll
        for (int i = 0; i < 4; i++) {
            const int c = tid + 256 * i;
            const int r = c >> 3, sg = c & 7;
            cpa16(smem_u32(Ad + r * LDA + sg * 4), X + (size_t)(m0 + r) * K + sg * 4);
            cpa16(smem_u32(Bd + r * LDA + sg * 4), W + (size_t)(n0 + r) * K + sg * 4);
        }
        CP_COMMIT();
    }

    for (int kt = 0; kt < NK; kt++) {
        const int p = kt & 1;
        if (kt + 1 < NK) {
            float* Ad = smem + (p ^ 1) * 2 * STAGE_FLOATS;
            float* Bd = Ad + STAGE_FLOATS;
            const int kcol = (kt + 1) * BK;
#pragma unroll
            for (int i = 0; i < 4; i++) {
                const int c = tid + 256 * i;
                const int r = c >> 3, sg = c & 7;
                cpa16(smem_u32(Ad + r * LDA + sg * 4), X + (size_t)(m0 + r) * K + kcol + sg * 4);
                cpa16(smem_u32(Bd + r * LDA + sg * 4), W + (size_t)(n0 + r) * K + kcol + sg * 4);
            }
            CP_COMMIT();
            CP_WAIT(1);
        } else {
            CP_WAIT(0);
        }
        __syncthreads();

        const float* Asm = smem + p * 2 * STAGE_FLOATS;
        const float* Bsm = Asm + STAGE_FLOATS;
#pragma unroll
        for (int kk = 0; kk < BK; kk += 8) {
            uint32_t afr[4][4], bfr[4][2];
#pragma unroll
            for (int i = 0; i < 4; i++) {
                const float* ap = Asm + (warp_m + i * 16 + g) * LDA + kk + tig;
                afr[i][0] = cvt_tf32(ap[0]);
                afr[i][1] = cvt_tf32(ap[8 * LDA]);
                afr[i][2] = cvt_tf32(ap[4]);
                afr[i][3] = cvt_tf32(ap[8 * LDA + 4]);
            }
#pragma unroll
            for (int j = 0; j < 4; j++) {
                const float* bp = Bsm + (warp_n + j * 8 + g) * LDA + kk + tig;
                bfr[j][0] = cvt_tf32(bp[0]);
                bfr[j][1] = cvt_tf32(bp[4]);
            }
#pragma unroll
            for (int i = 0; i < 4; i++)
#pragma unroll
                for (int j = 0; j < 4; j++)
                    mma_tf32(acc[i][j], afr[i], bfr[j]);
        }
        __syncthreads();
    }

    // epilogue: c0,c1 -> (row, col..col+1); c2,c3 -> (row+8, ...)
#pragma unroll
    for (int i = 0; i < 4; i++) {
#pragma unroll
        for (int j = 0; j < 4; j++) {
            const int row = m0 + warp_m + i * 16 + g;
            const int col = n0 + warp_n + j * 8 + 2 * tig;
            float2 v0, v1;
            v0.x = acc[i][j][0] * alpha; v0.y = acc[i][j][1] * alpha;
            v1.x = acc[i][j][2] * alpha; v1.y = acc[i][j][3] * alpha;
            *(float2*)(C + (size_t)row * N + col) = v0;
            *(float2*)(C + (size_t)(row + 8) * N + col) = v1;
        }
    }
}

// ---------------------------------------------------------------------------
// Lambda scalar
// ---------------------------------------------------------------------------
__global__ void lambda_kernel(const float* __restrict__ lq1, const float* __restrict__ lk1,
                              const float* __restrict__ lq2, const float* __restrict__ lk2)
{
    float s1 = 0.f, s2 = 0.f;
    for (int i = 0; i < Dc; i++) {
        s1 += lq1[i] * lk1[i];
        s2 += lq2[i] * lk2[i];
    }
    const float LI = 0.8f - 0.6f * expf(-3.6f);
    g_lam = expf(s1) - expf(s2) + LI;
}

// ---------------------------------------------------------------------------
// Causal flash attention (fp32, online softmax) — unchanged from R1
// ---------------------------------------------------------------------------
__global__ __launch_bounds__(256) void flash_kernel(
    const float* __restrict__ Q, const float* __restrict__ Km,
    const float* __restrict__ Vm, float* __restrict__ O)
{
    extern __shared__ float sm[];
    float* Qs = sm;           // [64 d][64 m]
    float* Ks = sm + 4096;    // [64 d][64 n]
    float* Ss = sm + 8192;    // [64 n][64 m]
    float* Vs = sm + 12288;   // [64 n][128 e]

    const int qtile = blockIdx.x;
    const int h2 = blockIdx.y;
    const int b = blockIdx.z;
    const int tid = threadIdx.x;
    const int tm = tid >> 4;
    const int tn = tid & 15;
    const int qm0 = qtile * 64;
    const int qoff = h2 * 64;
    const int voff = (h2 >> 1) * 128;

    {
        const int m = tid >> 2, q4 = tid & 3;
        const float* Qrow = Q + (size_t)(b * Tc + qm0 + m) * Ec + qoff;
#pragma unroll
        for (int j = 0; j < 4; j++) {
            const int f = q4 + 4 * j;
            float4 v = *(const float4*)(Qrow + f * 4);
            Qs[(f * 4 + 0) * 64 + m] = v.x;
            Qs[(f * 4 + 1) * 64 + m] = v.y;
            Qs[(f * 4 + 2) * 64 + m] = v.z;
            Qs[(f * 4 + 3) * 64 + m] = v.w;
        }
    }

    float acc[4][8];
#pragma unroll
    for (int i = 0; i < 4; i++)
#pragma unroll
        for (int j = 0; j < 8; j++) acc[i][j] = 0.f;
    float mrow[4] = {-1e30f, -1e30f, -1e30f, -1e30f};
    float lrow[4] = {0.f, 0.f, 0.f, 0.f};

    for (int kt = 0; kt <= qtile; kt++) {
        __syncthreads();

        {
            const int n = tid >> 2, q4 = tid & 3;
            const float* Krow = Km + (size_t)(b * Tc + kt * 64 + n) * Ec + qoff;
#pragma unroll
            for (int j = 0; j < 4; j++) {
                const int f = q4 + 4 * j;
                float4 v = *(const float4*)(Krow + f * 4);
                Ks[(f * 4 + 0) * 64 + n] = v.x;
                Ks[(f * 4 + 1) * 64 + n] = v.y;
                Ks[(f * 4 + 2) * 64 + n] = v.z;
                Ks[(f * 4 + 3) * 64 + n] = v.w;
            }
            const float* Vrow = Vm + (size_t)(b * Tc + kt * 64 + n) * Ec + voff;
#pragma unroll
            for (int j = 0; j < 8; j++) {
                const int f = q4 + 4 * j;
                *(float4*)(Vs + n * 128 + f * 4) = *(const float4*)(Vrow + f * 4);
            }
        }
        __syncthreads();

        float s[4][4];
#pragma unroll
        for (int i = 0; i < 4; i++)
#pragma unroll
            for (int j = 0; j < 4; j++) s[i][j] = 0.f;
#pragma unroll 8
        for (int d = 0; d < 64; d++) {
            float4 a = *(const float4*)(Qs + d * 64 + tm * 4);
            float4 kk = *(const float4*)(Ks + d * 64 + tn * 4);
            float ra[4] = {a.x, a.y, a.z, a.w};
            float rk[4] = {kk.x, kk.y, kk.z, kk.w};
#pragma unroll
            for (int i = 0; i < 4; i++)
#pragma unroll
                for (int j = 0; j < 4; j++)
                    s[i][j] = fmaf(ra[i], rk[j], s[i][j]);
        }

        if (kt == qtile) {
#pragma unroll
            for (int i = 0; i < 4; i++)
#pragma unroll
                for (int j = 0; j < 4; j++)
                    if (tn * 4 + j > tm * 4 + i) s[i][j] = -1e30f;
        }

#pragma unroll
        for (int i = 0; i < 4; i++) {
            float tmax = fmaxf(fmaxf(s[i][0], s[i][1]), fmaxf(s[i][2], s[i][3]));
#pragma unroll
            for (int off = 8; off > 0; off >>= 1)
                tmax = fmaxf(tmax, __shfl_xor_sync(0xffffffffu, tmax, off, 16));
            const float mnew = fmaxf(mrow[i], tmax);
            const float al = __expf(mrow[i] - mnew);
            float tsum = 0.f;
#pragma unroll
            for (int j = 0; j < 4; j++) {
                const float p = __expf(s[i][j] - mnew);
                s[i][j] = p;
                tsum += p;
            }
#pragma unroll
            for (int off = 8; off > 0; off >>= 1)
                tsum += __shfl_xor_sync(0xffffffffu, tsum, off, 16);
            lrow[i] = lrow[i] * al + tsum;
            mrow[i] = mnew;
#pragma unroll
            for (int j = 0; j < 8; j++) acc[i][j] *= al;
#pragma unroll
            for (int j = 0; j < 4; j++)
                Ss[(tn * 4 + j) * 64 + tm * 4 + i] = s[i][j];
        }
        __syncthreads();

#pragma unroll 4
        for (int n = 0; n < 64; n++) {
            float4 p4 = *(const float4*)(Ss + n * 64 + tm * 4);
            float4 v0 = *(const float4*)(Vs + n * 128 + tn * 8);
            float4 v1 = *(const float4*)(Vs + n * 128 + tn * 8 + 4);
            float pv[4] = {p4.x, p4.y, p4.z, p4.w};
            float vv[8] = {v0.x, v0.y, v0.z, v0.w, v1.x, v1.y, v1.z, v1.w};
#pragma unroll
            for (int i = 0; i < 4; i++)
#pragma unroll
                for (int j = 0; j < 8; j++)
                    acc[i][j] = fmaf(pv[i], vv[j], acc[i][j]);
        }
    }

#pragma unroll
    for (int i = 0; i < 4; i++) {
        const float inv = 1.f / lrow[i];
        float* dst = O + ((size_t)(b * 2 * Hc + h2) * Tc + qm0 + tm * 4 + i) * 128 + tn * 8;
        float4 o0, o1;
        o0.x = acc[i][0] * inv; o0.y = acc[i][1] * inv;
        o0.z = acc[i][2] * inv; o0.w = acc[i][3] * inv;
        o1.x = acc[i][4] * inv; o1.y = acc[i][5] * inv;
        o1.z = acc[i][6] * inv; o1.w = acc[i][7] * inv;
        *(float4*)(dst) = o0;
        *(float4*)(dst + 4) = o1;
    }
}

// ---------------------------------------------------------------------------
// Combine: x = O[2h] - lam*O[2h+1]; RMSNorm over 128; * g * (1-LI)
// ---------------------------------------------------------------------------
__global__ __launch_bounds__(128) void combine_kernel(
    const float* __restrict__ O, const float* __restrict__ g,
    float* __restrict__ ctx)
{
    const int idx = blockIdx.x;
    const int t = idx % Tc;
    const int h = (idx / Tc) % Hc;
    const int b = idx / (Tc * Hc);
    const int e = threadIdx.x;

    const size_t base1 = ((size_t)(b * 2 * Hc + 2 * h) * Tc + t) * 128;
    const size_t base2 = base1 + (size_t)Tc * 128;

    const float lam = g_lam;
    const float x = O[base1 + e] - lam * O[base2 + e];

    float v = x * x;
#pragma unroll
    for (int off = 16; off > 0; off >>= 1)
        v += __shfl_xor_sync(0xffffffffu, v, off, 32);

    __shared__ float red[4];
    if ((threadIdx.x & 31) == 0) red[threadIdx.x >> 5] = v;
    __syncthreads();
    const float tot = red[0] + red[1] + red[2] + red[3];
    const float rms = rsqrtf(tot * (1.f / 128.f) + 1e-5f);

    const float LI = 0.8f - 0.6f * expf(-3.6f);
    ctx[(size_t)(b * Tc + t) * Ec + h * 128 + e] = x * rms * g[e] * (1.f - LI);
}

// ---------------------------------------------------------------------------
// Host launcher
// ---------------------------------------------------------------------------
extern "C" void kernel_launch(void* const* d_in, const int* in_sizes, int n_in,
                              void* d_out, int out_size)
{
    (void)in_sizes; (void)n_in; (void)out_size;

    const float* query = (const float*)d_in[0];
    const float* Wq = (const float*)d_in[1];
    const float* Wk = (const float*)d_in[2];
    const float* Wv = (const float*)d_in[3];
    const float* Wo = (const float*)d_in[4];
    const float* lq1 = (const float*)d_in[5];
    const float* lk1 = (const float*)d_in[6];
    const float* lq2 = (const float*)d_in[7];
    const float* lk2 = (const float*)d_in[8];
    const float* gw = (const float*)d_in[9];
    float* out = (float*)d_out;

    float *pQ, *pK, *pV, *pO, *pC;
    cudaGetSymbolAddress((void**)&pQ, g_Q);
    cudaGetSymbolAddress((void**)&pK, g_K);
    cudaGetSymbolAddress((void**)&pV, g_V);
    cudaGetSymbolAddress((void**)&pO, g_O);
    cudaGetSymbolAddress((void**)&pC, g_ctx);

    cudaFuncSetAttribute(gemm_tf32mma, cudaFuncAttributeMaxDynamicSharedMemorySize, GSMEM_BYTES);

    const dim3 ggrid(Ec / 128, MTOT / 128);

    // projections (Q pre-scaled by D^-0.5 = 0.125)
    gemm_tf32mma<<<ggrid, 256, GSMEM_BYTES>>>(query, Wq, pQ, MTOT, Ec, Ec, 0.125f);
    gemm_tf32mma<<<ggrid, 256, GSMEM_BYTES>>>(query, Wk, pK, MTOT, Ec, Ec, 1.0f);
    gemm_tf32mma<<<ggrid, 256, GSMEM_BYTES>>>(query, Wv, pV, MTOT, Ec, Ec, 1.0f);

    lambda_kernel<<<1, 1>>>(lq1, lk1, lq2, lk2);

    const int FLASH_SMEM = 81920;
    cudaFuncSetAttribute(flash_kernel, cudaFuncAttributeMaxDynamicSharedMemorySize, FLASH_SMEM);
    flash_kernel<<<dim3(Tc / 64, 2 * Hc, Bc), 256, FLASH_SMEM>>>(pQ, pK, pV, pO);

    combine_kernel<<<Bc * Hc * Tc, 128>>>(pO, gw, pC);

    // output projection
    gemm_tf32mma<<<ggrid, 256, GSMEM_BYTES>>>(pC, Wo, out, MTOT, Ec, Ec, 1.0f);
}

// round 4
// speedup vs baseline: 2.8852x; 1.7282x over previous
#include <cuda_runtime.h>
#include <cstdint>
#include <math.h>

// Problem constants
#define Bc 2
#define Tc 2048
#define Ec 2048
#define Hc 16
#define Dc 64
#define MTOT (Bc * Tc)  // 4096

// ---------------------------------------------------------------------------
// Device scratch (no allocations allowed)
// ---------------------------------------------------------------------------
__device__ float g_Q[Bc * Tc * Ec];                       // [B*T, 2048] (pre-scaled)
__device__ float g_K[Bc * Tc * Ec];                       // [B*T, 2048]
__device__ float g_V[Bc * Tc * Ec];                       // [B*T, 2048]
__device__ float g_O[(size_t)Bc * 2 * Hc * Tc * 2 * Dc];  // [B, 2H, T, 128]
__device__ float g_ctx[Bc * Tc * Ec];                     // [B*T, 2048]
__device__ float g_lam;

// ---------------------------------------------------------------------------
// PTX helpers
// ---------------------------------------------------------------------------
__device__ __forceinline__ uint32_t smem_u32(const void* p) {
    uint32_t a;
    asm("{ .reg .u64 t; cvta.to.shared.u64 t, %1; cvt.u32.u64 %0, t; }" : "=r"(a) : "l"(p));
    return a;
}
__device__ __forceinline__ void cpa16(uint32_t saddr, const void* g) {
    asm volatile("cp.async.cg.shared.global [%0], [%1], 16;" :: "r"(saddr), "l"(g));
}
#define CP_COMMIT() asm volatile("cp.async.commit_group;" ::: "memory")
#define CP_WAIT(n) asm volatile("cp.async.wait_group %0;" :: "n"(n) : "memory")

__device__ __forceinline__ uint32_t cvt_tf32(float f) {
    uint32_t r;
    asm("cvt.rna.tf32.f32 %0, %1;" : "=r"(r) : "f"(f));
    return r;
}
__device__ __forceinline__ void mma_tf32(float* d, const uint32_t* a, const uint32_t* b) {
    asm volatile(
        "mma.sync.aligned.m16n8k8.row.col.f32.tf32.tf32.f32 "
        "{%0,%1,%2,%3}, {%4,%5,%6,%7}, {%8,%9}, {%0,%1,%2,%3};"
        : "+f"(d[0]), "+f"(d[1]), "+f"(d[2]), "+f"(d[3])
        : "r"(a[0]), "r"(a[1]), "r"(a[2]), "r"(a[3]), "r"(b[0]), "r"(b[1]));
}

// ---------------------------------------------------------------------------
// TF32 tensor-core GEMM: C[m,n] = alpha * sum_k X[m,k] * W[n,k]  (X @ W^T)
// CTA 128x128, BK=32, 8 warps (2x4), warp tile 64x32, m16n8k8 atoms.
// 3-stage cp.async pipeline; smem row stride 36 floats (conflict-free frags).
// ---------------------------------------------------------------------------
#define BM 128
#define BN 128
#define BK 32
#define LDA 36
#define STAGE_FLOATS (BM * LDA)                 // 4608 floats per matrix
#define GSMEM_BYTES (3 * 2 * STAGE_FLOATS * 4)  // 3 stages x (A+B) = 110592 B

__device__ __forceinline__ void g_stage_load(float* stage, const float* __restrict__ X,
                                             const float* __restrict__ W,
                                             int m0, int n0, int K, int kt, int tid) {
    float* Ad = stage;
    float* Bd = stage + STAGE_FLOATS;
    const int kcol = kt * BK;
#pragma unroll
    for (int i = 0; i < 4; i++) {
        const int c = tid + 256 * i;
        const int r = c >> 3, sg = c & 7;
        cpa16(smem_u32(Ad + r * LDA + sg * 4), X + (size_t)(m0 + r) * K + kcol + sg * 4);
        cpa16(smem_u32(Bd + r * LDA + sg * 4), W + (size_t)(n0 + r) * K + kcol + sg * 4);
    }
    CP_COMMIT();
}

__global__ __launch_bounds__(256) void gemm_tf32mma(
    const float* __restrict__ X, const float* __restrict__ W,
    float* __restrict__ C, int M, int N, int K, float alpha)
{
    extern __shared__ __align__(16) float smem[];
    const int tid = threadIdx.x;
    const int wid = tid >> 5;
    const int lane = tid & 31;
    const int g = lane >> 2;     // 0..7
    const int tig = lane & 3;    // 0..3
    const int warp_m = (wid & 1) * 64;
    const int warp_n = (wid >> 1) * 32;
    const int m0 = blockIdx.y * BM;
    const int n0 = blockIdx.x * BN;
    const int NK = K / BK;

    float acc[4][4][4];
#pragma unroll
    for (int i = 0; i < 4; i++)
#pragma unroll
        for (int j = 0; j < 4; j++)
#pragma unroll
            for (int r = 0; r < 4; r++) acc[i][j][r] = 0.f;

    // prologue: stages 0,1 <- kt 0,1
    g_stage_load(smem, X, W, m0, n0, K, 0, tid);
    g_stage_load(smem + 2 * STAGE_FLOATS, X, W, m0, n0, K, 1, tid);

    for (int kt = 0; kt < NK; kt++) {
        const int p = kt % 3;
        if (kt + 2 < NK) {
            g_stage_load(smem + ((kt + 2) % 3) * 2 * STAGE_FLOATS, X, W, m0, n0, K, kt + 2, tid);
            CP_WAIT(2);
        } else if (kt + 1 < NK) {
            CP_WAIT(1);
        } else {
            CP_WAIT(0);
        }
        __syncthreads();

        const float* Asm = smem + p * 2 * STAGE_FLOATS;
        const float* Bsm = Asm + STAGE_FLOATS;
#pragma unroll
        for (int kk = 0; kk < BK; kk += 8) {
            uint32_t afr[4][4], bfr[4][2];
#pragma unroll
            for (int i = 0; i < 4; i++) {
                const float* ap = Asm + (warp_m + i * 16 + g) * LDA + kk + tig;
                afr[i][0] = cvt_tf32(ap[0]);
                afr[i][1] = cvt_tf32(ap[8 * LDA]);
                afr[i][2] = cvt_tf32(ap[4]);
                afr[i][3] = cvt_tf32(ap[8 * LDA + 4]);
            }
#pragma unroll
            for (int j = 0; j < 4; j++) {
                const float* bp = Bsm + (warp_n + j * 8 + g) * LDA + kk + tig;
                bfr[j][0] = cvt_tf32(bp[0]);
                bfr[j][1] = cvt_tf32(bp[4]);
            }
#pragma unroll
            for (int i = 0; i < 4; i++)
#pragma unroll
                for (int j = 0; j < 4; j++)
                    mma_tf32(acc[i][j], afr[i], bfr[j]);
        }
        __syncthreads();
    }

#pragma unroll
    for (int i = 0; i < 4; i++) {
#pragma unroll
        for (int j = 0; j < 4; j++) {
            const int row = m0 + warp_m + i * 16 + g;
            const int col = n0 + warp_n + j * 8 + 2 * tig;
            float2 v0, v1;
            v0.x = acc[i][j][0] * alpha; v0.y = acc[i][j][1] * alpha;
            v1.x = acc[i][j][2] * alpha; v1.y = acc[i][j][3] * alpha;
            *(float2*)(C + (size_t)row * N + col) = v0;
            *(float2*)(C + (size_t)(row + 8) * N + col) = v1;
        }
    }
}

// ---------------------------------------------------------------------------
// Lambda scalar
// ---------------------------------------------------------------------------
__global__ void lambda_kernel(const float* __restrict__ lq1, const float* __restrict__ lk1,
                              const float* __restrict__ lq2, const float* __restrict__ lk2)
{
    float s1 = 0.f, s2 = 0.f;
    for (int i = 0; i < Dc; i++) {
        s1 += lq1[i] * lk1[i];
        s2 += lq2[i] * lk2[i];
    }
    const float LI = 0.8f - 0.6f * expf(-3.6f);
    g_lam = expf(s1) - expf(s2) + LI;
}

// ---------------------------------------------------------------------------
// Tensorized causal flash attention.
// Grid (T/64, 2H, B), 256 threads (8 warps).
// QK: warp grid 2(m=32) x 4(n=16); PV: warp grid 2(m=32) x 4(v=32).
// Q tf32 fragments held in registers for the whole block.
// smem floats: Qs[64][68], Ks[64][68], Ss[64][68], Vs[64][136], redm[4][64], reds[4][64]
// ---------------------------------------------------------------------------
#define FLDA 68
#define FVLD 136
#define FSMEM_FLOATS (3 * 64 * FLDA + 64 * FVLD + 512)
#define FSMEM_BYTES (FSMEM_FLOATS * 4)   // 89088

__global__ __launch_bounds__(256) void flash_mma(
    const float* __restrict__ Q, const float* __restrict__ Km,
    const float* __restrict__ Vm, float* __restrict__ O)
{
    extern __shared__ float sm[];
    float* Qs = sm;                      // 64*68
    float* Ks = Qs + 64 * FLDA;
    float* Ss = Ks + 64 * FLDA;
    float* Vs = Ss + 64 * FLDA;          // 64*136
    float* redm = Vs + 64 * FVLD;        // 4*64
    float* reds = redm + 256;            // 4*64

    const int qtile = blockIdx.x;
    const int h2 = blockIdx.y;
    const int b = blockIdx.z;
    const int tid = threadIdx.x;
    const int wid = tid >> 5;
    const int lane = tid & 31;
    const int g = lane >> 2;   // 0..7
    const int tig = lane & 3;  // 0..3
    const int wq = (wid & 1) * 32;
    const int wk = (wid >> 1) * 16;
    const int wv = (wid >> 1) * 32;
    const int wn = wid >> 1;
    const int qm0 = qtile * 64;
    const int qoff = h2 * 64;
    const int voff = (h2 >> 1) * 128;

    // ---- load Q tile (row-major, padded) ----
    {
        const int r = tid >> 2, q4 = tid & 3;
        const float* Qrow = Q + (size_t)(b * Tc + qm0 + r) * Ec + qoff;
#pragma unroll
        for (int j = 0; j < 4; j++)
            *(float4*)(Qs + r * FLDA + q4 * 16 + j * 4) = *(const float4*)(Qrow + q4 * 16 + j * 4);
    }
    __syncthreads();

    // ---- Q fragments in registers (converted once) ----
    uint32_t qfr[2][8][4];
#pragma unroll
    for (int i = 0; i < 2; i++) {
        const int r0 = wq + i * 16 + g;
#pragma unroll
        for (int kd = 0; kd < 8; kd++) {
            const float* p0 = Qs + r0 * FLDA + kd * 8 + tig;
            const float* p1 = Qs + (r0 + 8) * FLDA + kd * 8 + tig;
            qfr[i][kd][0] = cvt_tf32(p0[0]);
            qfr[i][kd][1] = cvt_tf32(p1[0]);
            qfr[i][kd][2] = cvt_tf32(p0[4]);
            qfr[i][kd][3] = cvt_tf32(p1[4]);
        }
    }

    float oacc[2][4][4];
#pragma unroll
    for (int i = 0; i < 2; i++)
#pragma unroll
        for (int j = 0; j < 4; j++)
#pragma unroll
            for (int r = 0; r < 4; r++) oacc[i][j][r] = 0.f;
    float mrow[4] = {-1e30f, -1e30f, -1e30f, -1e30f};  // [i*2 + half]
    float lrow[4] = {0.f, 0.f, 0.f, 0.f};

    for (int kt = 0; kt <= qtile; kt++) {
        __syncthreads();  // protect Ks/Vs/Ss/red from prev-iter readers

        // ---- load K, V tiles ----
        {
            const int r = tid >> 2, q4 = tid & 3;
            const float* Krow = Km + (size_t)(b * Tc + kt * 64 + r) * Ec + qoff;
#pragma unroll
            for (int j = 0; j < 4; j++)
                *(float4*)(Ks + r * FLDA + q4 * 16 + j * 4) = *(const float4*)(Krow + q4 * 16 + j * 4);
            const float* Vrow = Vm + (size_t)(b * Tc + kt * 64 + r) * Ec + voff;
#pragma unroll
            for (int j = 0; j < 8; j++)
                *(float4*)(Vs + r * FVLD + q4 * 4 + j * 16) = *(const float4*)(Vrow + q4 * 4 + j * 16);
        }
        __syncthreads();

        // ---- S = Q @ K^T (tf32 mma) ----
        float sacc[2][2][4];
#pragma unroll
        for (int i = 0; i < 2; i++)
#pragma unroll
            for (int j = 0; j < 2; j++)
#pragma unroll
                for (int r = 0; r < 4; r++) sacc[i][j][r] = 0.f;
#pragma unroll
        for (int kd = 0; kd < 8; kd++) {
            uint32_t bfr[2][2];
#pragma unroll
            for (int j = 0; j < 2; j++) {
                const float* bp = Ks + (wk + j * 8 + g) * FLDA + kd * 8 + tig;
                bfr[j][0] = cvt_tf32(bp[0]);
                bfr[j][1] = cvt_tf32(bp[4]);
            }
#pragma unroll
            for (int i = 0; i < 2; i++)
#pragma unroll
                for (int j = 0; j < 2; j++)
                    mma_tf32(sacc[i][j], qfr[i][kd], bfr[j]);
        }

        // ---- causal mask (diagonal tile only) ----
        if (kt == qtile) {
#pragma unroll
            for (int i = 0; i < 2; i++)
#pragma unroll
                for (int j = 0; j < 2; j++) {
                    const int colb = wk + j * 8 + 2 * tig;
                    const int row0 = wq + i * 16 + g;
                    if (colb > row0) sacc[i][j][0] = -1e30f;
                    if (colb + 1 > row0) sacc[i][j][1] = -1e30f;
                    if (colb > row0 + 8) sacc[i][j][2] = -1e30f;
                    if (colb + 1 > row0 + 8) sacc[i][j][3] = -1e30f;
                }
        }

        // ---- warp-slice row max over (j, tig) ----
#pragma unroll
        for (int i = 0; i < 2; i++) {
            float m0 = fmaxf(fmaxf(sacc[i][0][0], sacc[i][0][1]), fmaxf(sacc[i][1][0], sacc[i][1][1]));
            float m1 = fmaxf(fmaxf(sacc[i][0][2], sacc[i][0][3]), fmaxf(sacc[i][1][2], sacc[i][1][3]));
#pragma unroll
            for (int off = 1; off <= 2; off <<= 1) {
                m0 = fmaxf(m0, __shfl_xor_sync(0xffffffffu, m0, off));
                m1 = fmaxf(m1, __shfl_xor_sync(0xffffffffu, m1, off));
            }
            if (tig == 0) {
                redm[wn * 64 + wq + i * 16 + g] = m0;
                redm[wn * 64 + wq + i * 16 + 8 + g] = m1;
            }
        }
        __syncthreads();

        // ---- combine max across 4 n-warps; rescale factors ----
        float al[4];
#pragma unroll
        for (int i = 0; i < 2; i++)
#pragma unroll
            for (int h = 0; h < 2; h++) {
                const int r = wq + i * 16 + h * 8 + g;
                const float tm = fmaxf(fmaxf(redm[r], redm[64 + r]),
                                       fmaxf(redm[128 + r], redm[192 + r]));
                const int si = i * 2 + h;
                const float mnew = fmaxf(mrow[si], tm);
                al[si] = __expf(mrow[si] - mnew);
                mrow[si] = mnew;
            }

        // ---- exp, store P to smem, slice sums ----
#pragma unroll
        for (int i = 0; i < 2; i++) {
            float s0 = 0.f, s1 = 0.f;
            const int r0 = wq + i * 16 + g;
#pragma unroll
            for (int j = 0; j < 2; j++) {
                const int col = wk + j * 8 + 2 * tig;
                const float p00 = __expf(sacc[i][j][0] - mrow[i * 2]);
                const float p01 = __expf(sacc[i][j][1] - mrow[i * 2]);
                const float p10 = __expf(sacc[i][j][2] - mrow[i * 2 + 1]);
                const float p11 = __expf(sacc[i][j][3] - mrow[i * 2 + 1]);
                s0 += p00 + p01;
                s1 += p10 + p11;
                *(float2*)(Ss + r0 * FLDA + col) = make_float2(p00, p01);
                *(float2*)(Ss + (r0 + 8) * FLDA + col) = make_float2(p10, p11);
            }
#pragma unroll
            for (int off = 1; off <= 2; off <<= 1) {
                s0 += __shfl_xor_sync(0xffffffffu, s0, off);
                s1 += __shfl_xor_sync(0xffffffffu, s1, off);
            }
            if (tig == 0) {
                reds[wn * 64 + wq + i * 16 + g] = s0;
                reds[wn * 64 + wq + i * 16 + 8 + g] = s1;
            }
        }
        __syncthreads();

        // ---- total sums; update l; rescale O accumulators ----
#pragma unroll
        for (int i = 0; i < 2; i++)
#pragma unroll
            for (int h = 0; h < 2; h++) {
                const int r = wq + i * 16 + h * 8 + g;
                const float ts = reds[r] + reds[64 + r] + reds[128 + r] + reds[192 + r];
                const int si = i * 2 + h;
                lrow[si] = lrow[si] * al[si] + ts;
            }
#pragma unroll
        for (int i = 0; i < 2; i++)
#pragma unroll
            for (int jv = 0; jv < 4; jv++) {
                oacc[i][jv][0] *= al[i * 2];
                oacc[i][jv][1] *= al[i * 2];
                oacc[i][jv][2] *= al[i * 2 + 1];
                oacc[i][jv][3] *= al[i * 2 + 1];
            }

        // ---- O += P @ V (tf32 mma) ----
#pragma unroll
        for (int kn = 0; kn < 8; kn++) {
            uint32_t afr[2][4];
#pragma unroll
            for (int i = 0; i < 2; i++) {
                const int r0 = wq + i * 16 + g;
                const float* p0 = Ss + r0 * FLDA + kn * 8 + tig;
                const float* p1 = Ss + (r0 + 8) * FLDA + kn * 8 + tig;
                afr[i][0] = cvt_tf32(p0[0]);
                afr[i][1] = cvt_tf32(p1[0]);
                afr[i][2] = cvt_tf32(p0[4]);
                afr[i][3] = cvt_tf32(p1[4]);
            }
#pragma unroll
            for (int jv = 0; jv < 4; jv++) {
                uint32_t bfr[2];
                const float* bp = Vs + (kn * 8 + tig) * FVLD + wv + jv * 8 + g;
                bfr[0] = cvt_tf32(bp[0]);
                bfr[1] = cvt_tf32(bp[4 * FVLD]);
#pragma unroll
                for (int i = 0; i < 2; i++)
                    mma_tf32(oacc[i][jv], afr[i], bfr);
            }
        }
    }

    // ---- epilogue ----
#pragma unroll
    for (int i = 0; i < 2; i++) {
        const float inv0 = 1.f / lrow[i * 2];
        const float inv1 = 1.f / lrow[i * 2 + 1];
        const int r0 = wq + i * 16 + g;
#pragma unroll
        for (int jv = 0; jv < 4; jv++) {
            const int col = wv + jv * 8 + 2 * tig;
            float* d0 = O + ((size_t)(b * 2 * Hc + h2) * Tc + qm0 + r0) * 128 + col;
            float* d1 = O + ((size_t)(b * 2 * Hc + h2) * Tc + qm0 + r0 + 8) * 128 + col;
            *(float2*)d0 = make_float2(oacc[i][jv][0] * inv0, oacc[i][jv][1] * inv0);
            *(float2*)d1 = make_float2(oacc[i][jv][2] * inv1, oacc[i][jv][3] * inv1);
        }
    }
}

// ---------------------------------------------------------------------------
// Combine: x = O[2h] - lam*O[2h+1]; RMSNorm over 128; * g * (1-LI)
// ---------------------------------------------------------------------------
__global__ __launch_bounds__(128) void combine_kernel(
    const float* __restrict__ O, const float* __restrict__ g,
    float* __restrict__ ctx)
{
    const int idx = blockIdx.x;
    const int t = idx % Tc;
    const int h = (idx / Tc) % Hc;
    const int b = idx / (Tc * Hc);
    const int e = threadIdx.x;

    const size_t base1 = ((size_t)(b * 2 * Hc + 2 * h) * Tc + t) * 128;
    const size_t base2 = base1 + (size_t)Tc * 128;

    const float lam = g_lam;
    const float x = O[base1 + e] - lam * O[base2 + e];

    float v = x * x;
#pragma unroll
    for (int off = 16; off > 0; off >>= 1)
        v += __shfl_xor_sync(0xffffffffu, v, off, 32);

    __shared__ float red[4];
    if ((threadIdx.x & 31) == 0) red[threadIdx.x >> 5] = v;
    __syncthreads();
    const float tot = red[0] + red[1] + red[2] + red[3];
    const float rms = rsqrtf(tot * (1.f / 128.f) + 1e-5f);

    const float LI = 0.8f - 0.6f * expf(-3.6f);
    ctx[(size_t)(b * Tc + t) * Ec + h * 128 + e] = x * rms * g[e] * (1.f - LI);
}

// ---------------------------------------------------------------------------
// Host launcher
// ---------------------------------------------------------------------------
extern "C" void kernel_launch(void* const* d_in, const int* in_sizes, int n_in,
                              void* d_out, int out_size)
{
    (void)in_sizes; (void)n_in; (void)out_size;

    const float* query = (const float*)d_in[0];
    const float* Wq = (const float*)d_in[1];
    const float* Wk = (const float*)d_in[2];
    const float* Wv = (const float*)d_in[3];
    const float* Wo = (const float*)d_in[4];
    const float* lq1 = (const float*)d_in[5];
    const float* lk1 = (const float*)d_in[6];
    const float* lq2 = (const float*)d_in[7];
    const float* lk2 = (const float*)d_in[8];
    const float* gw = (const float*)d_in[9];
    float* out = (float*)d_out;

    float *pQ, *pK, *pV, *pO, *pC;
    cudaGetSymbolAddress((void**)&pQ, g_Q);
    cudaGetSymbolAddress((void**)&pK, g_K);
    cudaGetSymbolAddress((void**)&pV, g_V);
    cudaGetSymbolAddress((void**)&pO, g_O);
    cudaGetSymbolAddress((void**)&pC, g_ctx);

    cudaFuncSetAttribute(gemm_tf32mma, cudaFuncAttributeMaxDynamicSharedMemorySize, GSMEM_BYTES);
    cudaFuncSetAttribute(flash_mma, cudaFuncAttributeMaxDynamicSharedMemorySize, FSMEM_BYTES);

    const dim3 ggrid(Ec / 128, MTOT / 128);

    // projections (Q pre-scaled by D^-0.5 = 0.125)
    gemm_tf32mma<<<ggrid, 256, GSMEM_BYTES>>>(query, Wq, pQ, MTOT, Ec, Ec, 0.125f);
    gemm_tf32mma<<<ggrid, 256, GSMEM_BYTES>>>(query, Wk, pK, MTOT, Ec, Ec, 1.0f);
    gemm_tf32mma<<<ggrid, 256, GSMEM_BYTES>>>(query, Wv, pV, MTOT, Ec, Ec, 1.0f);

    lambda_kernel<<<1, 1>>>(lq1, lk1, lq2, lk2);

    flash_mma<<<dim3(Tc / 64, 2 * Hc, Bc), 256, FSMEM_BYTES>>>(pQ, pK, pV, pO);

    combine_kernel<<<Bc * Hc * Tc, 128>>>(pO, gw, pC);

    // output projection
    gemm_tf32mma<<<ggrid, 256, GSMEM_BYTES>>>(pC, Wo, out, MTOT, Ec, Ec, 1.0f);
}

// round 5
// speedup vs baseline: 3.0592x; 1.0603x over previous
#include <cuda_runtime.h>
#include <cstdint>
#include <math.h>

// Problem constants
#define Bc 2
#define Tc 2048
#define Ec 2048
#define Hc 16
#define Dc 64
#define MTOT (Bc * Tc)  // 4096

// ---------------------------------------------------------------------------
// Device scratch (no allocations allowed)
// ---------------------------------------------------------------------------
__device__ float g_Q[Bc * Tc * Ec];                       // [B*T, 2048] (pre-scaled, tf32-rounded)
__device__ float g_K[Bc * Tc * Ec];                       // tf32-rounded
__device__ float g_V[Bc * Tc * Ec];                       // tf32-rounded
__device__ float g_O[(size_t)Bc * 2 * Hc * Tc * 2 * Dc];  // [B, 2H, T, 128]
__device__ float g_ctx[Bc * Tc * Ec];                     // tf32-rounded
__device__ float g_Xr[MTOT * Ec];                         // rounded query
__device__ float g_Wr[Ec * Ec];                           // rounded weight (reused serially)
__device__ float g_lam;

// ---------------------------------------------------------------------------
// PTX helpers
// ---------------------------------------------------------------------------
__device__ __forceinline__ uint32_t smem_u32(const void* p) {
    uint32_t a;
    asm("{ .reg .u64 t; cvta.to.shared.u64 t, %1; cvt.u32.u64 %0, t; }" : "=r"(a) : "l"(p));
    return a;
}
__device__ __forceinline__ void cpa16(uint32_t saddr, const void* g) {
    asm volatile("cp.async.cg.shared.global [%0], [%1], 16;" :: "r"(saddr), "l"(g));
}
#define CP_COMMIT() asm volatile("cp.async.commit_group;" ::: "memory")
#define CP_WAIT(n) asm volatile("cp.async.wait_group %0;" :: "n"(n) : "memory")

__device__ __forceinline__ uint32_t cvt_tf32(float f) {
    uint32_t r;
    asm("cvt.rna.tf32.f32 %0, %1;" : "=r"(r) : "f"(f));
    return r;
}
__device__ __forceinline__ float round_tf32f(float f) {
    return __uint_as_float(cvt_tf32(f));
}
__device__ __forceinline__ void mma_tf32(float* d, const uint32_t* a, const uint32_t* b) {
    asm volatile(
        "mma.sync.aligned.m16n8k8.row.col.f32.tf32.tf32.f32 "
        "{%0,%1,%2,%3}, {%4,%5,%6,%7}, {%8,%9}, {%0,%1,%2,%3};"
        : "+f"(d[0]), "+f"(d[1]), "+f"(d[2]), "+f"(d[3])
        : "r"(a[0]), "r"(a[1]), "r"(a[2]), "r"(a[3]), "r"(b[0]), "r"(b[1]));
}

// ---------------------------------------------------------------------------
// Round a buffer to tf32 values (rna), 1:1 copy.
// ---------------------------------------------------------------------------
__global__ __launch_bounds__(256) void round_tf32_kernel(
    const float* __restrict__ in, float* __restrict__ out, int n4)
{
    const int i = blockIdx.x * 256 + threadIdx.x;
    if (i < n4) {
        float4 v = *(const float4*)(in + 4 * (size_t)i);
        v.x = round_tf32f(v.x);
        v.y = round_tf32f(v.y);
        v.z = round_tf32f(v.z);
        v.w = round_tf32f(v.w);
        *(float4*)(out + 4 * (size_t)i) = v;
    }
}

// ---------------------------------------------------------------------------
// TF32 tensor-core GEMM: C[m,n] = alpha * sum_k X[m,k] * W[n,k]  (X @ W^T)
// Inputs MUST already be tf32-rounded; fragments are raw bit loads (no cvt).
// CTA 128x128, BK=32, 8 warps (2x4), warp tile 64x32, 3-stage cp.async.
// round_out != 0 -> round outputs to tf32 (for tensor-core consumers).
// ---------------------------------------------------------------------------
#define BM 128
#define BN 128
#define BK 32
#define LDA 36
#define STAGE_FLOATS (BM * LDA)                 // 4608 floats per matrix
#define GSMEM_BYTES (3 * 2 * STAGE_FLOATS * 4)  // 110592 B

__device__ __forceinline__ void g_stage_load(float* stage, const float* __restrict__ X,
                                             const float* __restrict__ W,
                                             int m0, int n0, int K, int kt, int tid) {
    float* Ad = stage;
    float* Bd = stage + STAGE_FLOATS;
    const int kcol = kt * BK;
#pragma unroll
    for (int i = 0; i < 4; i++) {
        const int c = tid + 256 * i;
        const int r = c >> 3, sg = c & 7;
        cpa16(smem_u32(Ad + r * LDA + sg * 4), X + (size_t)(m0 + r) * K + kcol + sg * 4);
        cpa16(smem_u32(Bd + r * LDA + sg * 4), W + (size_t)(n0 + r) * K + kcol + sg * 4);
    }
    CP_COMMIT();
}

__global__ __launch_bounds__(256) void gemm_tf32mma(
    const float* __restrict__ X, const float* __restrict__ W,
    float* __restrict__ C, int M, int N, int K, float alpha, int round_out)
{
    extern __shared__ __align__(16) float smem[];
    const int tid = threadIdx.x;
    const int wid = tid >> 5;
    const int lane = tid & 31;
    const int g = lane >> 2;     // 0..7
    const int tig = lane & 3;    // 0..3
    const int warp_m = (wid & 1) * 64;
    const int warp_n = (wid >> 1) * 32;
    const int m0 = blockIdx.y * BM;
    const int n0 = blockIdx.x * BN;
    const int NK = K / BK;

    float acc[4][4][4];
#pragma unroll
    for (int i = 0; i < 4; i++)
#pragma unroll
        for (int j = 0; j < 4; j++)
#pragma unroll
            for (int r = 0; r < 4; r++) acc[i][j][r] = 0.f;

    // prologue: stages 0,1 <- kt 0,1
    g_stage_load(smem, X, W, m0, n0, K, 0, tid);
    g_stage_load(smem + 2 * STAGE_FLOATS, X, W, m0, n0, K, 1, tid);

    for (int kt = 0; kt < NK; kt++) {
        const int p = kt % 3;
        if (kt + 2 < NK) {
            g_stage_load(smem + ((kt + 2) % 3) * 2 * STAGE_FLOATS, X, W, m0, n0, K, kt + 2, tid);
            CP_WAIT(2);
        } else if (kt + 1 < NK) {
            CP_WAIT(1);
        } else {
            CP_WAIT(0);
        }
        __syncthreads();

        const uint32_t* Asm = (const uint32_t*)(smem + p * 2 * STAGE_FLOATS);
        const uint32_t* Bsm = Asm + STAGE_FLOATS;
#pragma unroll
        for (int kk = 0; kk < BK; kk += 8) {
            uint32_t afr[4][4], bfr[4][2];
#pragma unroll
            for (int i = 0; i < 4; i++) {
                const uint32_t* ap = Asm + (warp_m + i * 16 + g) * LDA + kk + tig;
                afr[i][0] = ap[0];
                afr[i][1] = ap[8 * LDA];
                afr[i][2] = ap[4];
                afr[i][3] = ap[8 * LDA + 4];
            }
#pragma unroll
            for (int j = 0; j < 4; j++) {
                const uint32_t* bp = Bsm + (warp_n + j * 8 + g) * LDA + kk + tig;
                bfr[j][0] = bp[0];
                bfr[j][1] = bp[4];
            }
#pragma unroll
            for (int i = 0; i < 4; i++)
#pragma unroll
                for (int j = 0; j < 4; j++)
                    mma_tf32(acc[i][j], afr[i], bfr[j]);
        }
        __syncthreads();
    }

#pragma unroll
    for (int i = 0; i < 4; i++) {
#pragma unroll
        for (int j = 0; j < 4; j++) {
            const int row = m0 + warp_m + i * 16 + g;
            const int col = n0 + warp_n + j * 8 + 2 * tig;
            float2 v0, v1;
            v0.x = acc[i][j][0] * alpha; v0.y = acc[i][j][1] * alpha;
            v1.x = acc[i][j][2] * alpha; v1.y = acc[i][j][3] * alpha;
            if (round_out) {
                v0.x = round_tf32f(v0.x); v0.y = round_tf32f(v0.y);
                v1.x = round_tf32f(v1.x); v1.y = round_tf32f(v1.y);
            }
            *(float2*)(C + (size_t)row * N + col) = v0;
            *(float2*)(C + (size_t)(row + 8) * N + col) = v1;
        }
    }
}

// ---------------------------------------------------------------------------
// Lambda scalar
// ---------------------------------------------------------------------------
__global__ void lambda_kernel(const float* __restrict__ lq1, const float* __restrict__ lk1,
                              const float* __restrict__ lq2, const float* __restrict__ lk2)
{
    float s1 = 0.f, s2 = 0.f;
    for (int i = 0; i < Dc; i++) {
        s1 += lq1[i] * lk1[i];
        s2 += lq2[i] * lk2[i];
    }
    const float LI = 0.8f - 0.6f * expf(-3.6f);
    g_lam = expf(s1) - expf(s2) + LI;
}

// ---------------------------------------------------------------------------
// Tensorized causal flash attention. Inputs tf32-rounded -> raw-bit fragments.
// Grid (T/64, 2H, B), 256 threads (8 warps).
// ---------------------------------------------------------------------------
#define FLDA 68
#define FVLD 136
#define FSMEM_FLOATS (3 * 64 * FLDA + 64 * FVLD + 512)
#define FSMEM_BYTES (FSMEM_FLOATS * 4)   // 89088

__global__ __launch_bounds__(256) void flash_mma(
    const float* __restrict__ Q, const float* __restrict__ Km,
    const float* __restrict__ Vm, float* __restrict__ O)
{
    extern __shared__ float sm[];
    float* Qs = sm;                      // 64*68
    float* Ks = Qs + 64 * FLDA;
    float* Ss = Ks + 64 * FLDA;
    float* Vs = Ss + 64 * FLDA;          // 64*136
    float* redm = Vs + 64 * FVLD;        // 4*64
    float* reds = redm + 256;            // 4*64

    const int qtile = blockIdx.x;
    const int h2 = blockIdx.y;
    const int b = blockIdx.z;
    const int tid = threadIdx.x;
    const int wid = tid >> 5;
    const int lane = tid & 31;
    const int g = lane >> 2;   // 0..7
    const int tig = lane & 3;  // 0..3
    const int wq = (wid & 1) * 32;
    const int wk = (wid >> 1) * 16;
    const int wv = (wid >> 1) * 32;
    const int wn = wid >> 1;
    const int qm0 = qtile * 64;
    const int qoff = h2 * 64;
    const int voff = (h2 >> 1) * 128;

    // ---- load Q tile (row-major, padded) ----
    {
        const int r = tid >> 2, q4 = tid & 3;
        const float* Qrow = Q + (size_t)(b * Tc + qm0 + r) * Ec + qoff;
#pragma unroll
        for (int j = 0; j < 4; j++)
            *(float4*)(Qs + r * FLDA + q4 * 16 + j * 4) = *(const float4*)(Qrow + q4 * 16 + j * 4);
    }
    __syncthreads();

    // ---- Q fragments in registers (raw bits; already tf32-rounded) ----
    uint32_t qfr[2][8][4];
#pragma unroll
    for (int i = 0; i < 2; i++) {
        const int r0 = wq + i * 16 + g;
#pragma unroll
        for (int kd = 0; kd < 8; kd++) {
            const uint32_t* p0 = (const uint32_t*)(Qs + r0 * FLDA + kd * 8 + tig);
            const uint32_t* p1 = (const uint32_t*)(Qs + (r0 + 8) * FLDA + kd * 8 + tig);
            qfr[i][kd][0] = p0[0];
            qfr[i][kd][1] = p1[0];
            qfr[i][kd][2] = p0[4];
            qfr[i][kd][3] = p1[4];
        }
    }

    float oacc[2][4][4];
#pragma unroll
    for (int i = 0; i < 2; i++)
#pragma unroll
        for (int j = 0; j < 4; j++)
#pragma unroll
            for (int r = 0; r < 4; r++) oacc[i][j][r] = 0.f;
    float mrow[4] = {-1e30f, -1e30f, -1e30f, -1e30f};  // [i*2 + half]
    float lrow[4] = {0.f, 0.f, 0.f, 0.f};

    for (int kt = 0; kt <= qtile; kt++) {
        __syncthreads();

        // ---- load K, V tiles ----
        {
            const int r = tid >> 2, q4 = tid & 3;
            const float* Krow = Km + (size_t)(b * Tc + kt * 64 + r) * Ec + qoff;
#pragma unroll
            for (int j = 0; j < 4; j++)
                *(float4*)(Ks + r * FLDA + q4 * 16 + j * 4) = *(const float4*)(Krow + q4 * 16 + j * 4);
            const float* Vrow = Vm + (size_t)(b * Tc + kt * 64 + r) * Ec + voff;
#pragma unroll
            for (int j = 0; j < 8; j++)
                *(float4*)(Vs + r * FVLD + q4 * 4 + j * 16) = *(const float4*)(Vrow + q4 * 4 + j * 16);
        }
        __syncthreads();

        // ---- S = Q @ K^T (tf32 mma, raw-bit B frags) ----
        float sacc[2][2][4];
#pragma unroll
        for (int i = 0; i < 2; i++)
#pragma unroll
            for (int j = 0; j < 2; j++)
#pragma unroll
                for (int r = 0; r < 4; r++) sacc[i][j][r] = 0.f;
#pragma unroll
        for (int kd = 0; kd < 8; kd++) {
            uint32_t bfr[2][2];
#pragma unroll
            for (int j = 0; j < 2; j++) {
                const uint32_t* bp = (const uint32_t*)(Ks + (wk + j * 8 + g) * FLDA + kd * 8 + tig);
                bfr[j][0] = bp[0];
                bfr[j][1] = bp[4];
            }
#pragma unroll
            for (int i = 0; i < 2; i++)
#pragma unroll
                for (int j = 0; j < 2; j++)
                    mma_tf32(sacc[i][j], qfr[i][kd], bfr[j]);
        }

        // ---- causal mask (diagonal tile only) ----
        if (kt == qtile) {
#pragma unroll
            for (int i = 0; i < 2; i++)
#pragma unroll
                for (int j = 0; j < 2; j++) {
                    const int colb = wk + j * 8 + 2 * tig;
                    const int row0 = wq + i * 16 + g;
                    if (colb > row0) sacc[i][j][0] = -1e30f;
                    if (colb + 1 > row0) sacc[i][j][1] = -1e30f;
                    if (colb > row0 + 8) sacc[i][j][2] = -1e30f;
                    if (colb + 1 > row0 + 8) sacc[i][j][3] = -1e30f;
                }
        }

        // ---- warp-slice row max over (j, tig) ----
#pragma unroll
        for (int i = 0; i < 2; i++) {
            float m0 = fmaxf(fmaxf(sacc[i][0][0], sacc[i][0][1]), fmaxf(sacc[i][1][0], sacc[i][1][1]));
            float m1 = fmaxf(fmaxf(sacc[i][0][2], sacc[i][0][3]), fmaxf(sacc[i][1][2], sacc[i][1][3]));
#pragma unroll
            for (int off = 1; off <= 2; off <<= 1) {
                m0 = fmaxf(m0, __shfl_xor_sync(0xffffffffu, m0, off));
                m1 = fmaxf(m1, __shfl_xor_sync(0xffffffffu, m1, off));
            }
            if (tig == 0) {
                redm[wn * 64 + wq + i * 16 + g] = m0;
                redm[wn * 64 + wq + i * 16 + 8 + g] = m1;
            }
        }
        __syncthreads();

        // ---- combine max across 4 n-warps; rescale factors ----
        float al[4];
#pragma unroll
        for (int i = 0; i < 2; i++)
#pragma unroll
            for (int h = 0; h < 2; h++) {
                const int r = wq + i * 16 + h * 8 + g;
                const float tm = fmaxf(fmaxf(redm[r], redm[64 + r]),
                                       fmaxf(redm[128 + r], redm[192 + r]));
                const int si = i * 2 + h;
                const float mnew = fmaxf(mrow[si], tm);
                al[si] = __expf(mrow[si] - mnew);
                mrow[si] = mnew;
            }

        // ---- exp, store tf32-rounded P to smem, slice sums ----
#pragma unroll
        for (int i = 0; i < 2; i++) {
            float s0 = 0.f, s1 = 0.f;
            const int r0 = wq + i * 16 + g;
#pragma unroll
            for (int j = 0; j < 2; j++) {
                const int col = wk + j * 8 + 2 * tig;
                const float p00 = __expf(sacc[i][j][0] - mrow[i * 2]);
                const float p01 = __expf(sacc[i][j][1] - mrow[i * 2]);
                const float p10 = __expf(sacc[i][j][2] - mrow[i * 2 + 1]);
                const float p11 = __expf(sacc[i][j][3] - mrow[i * 2 + 1]);
                s0 += p00 + p01;
                s1 += p10 + p11;
                *(float2*)(Ss + r0 * FLDA + col) =
                    make_float2(round_tf32f(p00), round_tf32f(p01));
                *(float2*)(Ss + (r0 + 8) * FLDA + col) =
                    make_float2(round_tf32f(p10), round_tf32f(p11));
            }
#pragma unroll
            for (int off = 1; off <= 2; off <<= 1) {
                s0 += __shfl_xor_sync(0xffffffffu, s0, off);
                s1 += __shfl_xor_sync(0xffffffffu, s1, off);
            }
            if (tig == 0) {
                reds[wn * 64 + wq + i * 16 + g] = s0;
                reds[wn * 64 + wq + i * 16 + 8 + g] = s1;
            }
        }
        __syncthreads();

        // ---- total sums; update l; rescale O accumulators ----
#pragma unroll
        for (int i = 0; i < 2; i++)
#pragma unroll
            for (int h = 0; h < 2; h++) {
                const int r = wq + i * 16 + h * 8 + g;
                const float ts = reds[r] + reds[64 + r] + reds[128 + r] + reds[192 + r];
                const int si = i * 2 + h;
                lrow[si] = lrow[si] * al[si] + ts;
            }
#pragma unroll
        for (int i = 0; i < 2; i++)
#pragma unroll
            for (int jv = 0; jv < 4; jv++) {
                oacc[i][jv][0] *= al[i * 2];
                oacc[i][jv][1] *= al[i * 2];
                oacc[i][jv][2] *= al[i * 2 + 1];
                oacc[i][jv][3] *= al[i * 2 + 1];
            }

        // ---- O += P @ V (tf32 mma, raw-bit frags) ----
#pragma unroll
        for (int kn = 0; kn < 8; kn++) {
            uint32_t afr[2][4];
#pragma unroll
            for (int i = 0; i < 2; i++) {
                const int r0 = wq + i * 16 + g;
                const uint32_t* p0 = (const uint32_t*)(Ss + r0 * FLDA + kn * 8 + tig);
                const uint32_t* p1 = (const uint32_t*)(Ss + (r0 + 8) * FLDA + kn * 8 + tig);
                afr[i][0] = p0[0];
                afr[i][1] = p1[0];
                afr[i][2] = p0[4];
                afr[i][3] = p1[4];
            }
#pragma unroll
            for (int jv = 0; jv < 4; jv++) {
                uint32_t bfr[2];
                const uint32_t* bp = (const uint32_t*)(Vs + (kn * 8 + tig) * FVLD + wv + jv * 8 + g);
                bfr[0] = bp[0];
                bfr[1] = bp[4 * FVLD];
#pragma unroll
                for (int i = 0; i < 2; i++)
                    mma_tf32(oacc[i][jv], afr[i], bfr);
            }
        }
    }

    // ---- epilogue ----
#pragma unroll
    for (int i = 0; i < 2; i++) {
        const float inv0 = 1.f / lrow[i * 2];
        const float inv1 = 1.f / lrow[i * 2 + 1];
        const int r0 = wq + i * 16 + g;
#pragma unroll
        for (int jv = 0; jv < 4; jv++) {
            const int col = wv + jv * 8 + 2 * tig;
            float* d0 = O + ((size_t)(b * 2 * Hc + h2) * Tc + qm0 + r0) * 128 + col;
            float* d1 = O + ((size_t)(b * 2 * Hc + h2) * Tc + qm0 + r0 + 8) * 128 + col;
            *(float2*)d0 = make_float2(oacc[i][jv][0] * inv0, oacc[i][jv][1] * inv0);
            *(float2*)d1 = make_float2(oacc[i][jv][2] * inv1, oacc[i][jv][3] * inv1);
        }
    }
}

// ---------------------------------------------------------------------------
// Combine: x = O[2h] - lam*O[2h+1]; RMSNorm over 128; * g * (1-LI)
// Output rounded to tf32 (consumed by tensor-core GEMM).
// ---------------------------------------------------------------------------
__global__ __launch_bounds__(128) void combine_kernel(
    const float* __restrict__ O, const float* __restrict__ g,
    float* __restrict__ ctx)
{
    const int idx = blockIdx.x;
    const int t = idx % Tc;
    const int h = (idx / Tc) % Hc;
    const int b = idx / (Tc * Hc);
    const int e = threadIdx.x;

    const size_t base1 = ((size_t)(b * 2 * Hc + 2 * h) * Tc + t) * 128;
    const size_t base2 = base1 + (size_t)Tc * 128;

    const float lam = g_lam;
    const float x = O[base1 + e] - lam * O[base2 + e];

    float v = x * x;
#pragma unroll
    for (int off = 16; off > 0; off >>= 1)
        v += __shfl_xor_sync(0xffffffffu, v, off, 32);

    __shared__ float red[4];
    if ((threadIdx.x & 31) == 0) red[threadIdx.x >> 5] = v;
    __syncthreads();
    const float tot = red[0] + red[1] + red[2] + red[3];
    const float rms = rsqrtf(tot * (1.f / 128.f) + 1e-5f);

    const float LI = 0.8f - 0.6f * expf(-3.6f);
    ctx[(size_t)(b * Tc + t) * Ec + h * 128 + e] =
        round_tf32f(x * rms * g[e] * (1.f - LI));
}

// ---------------------------------------------------------------------------
// Host launcher
// ---------------------------------------------------------------------------
extern "C" void kernel_launch(void* const* d_in, const int* in_sizes, int n_in,
                              void* d_out, int out_size)
{
    (void)in_sizes; (void)n_in; (void)out_size;

    const float* query = (const float*)d_in[0];
    const float* Wq = (const float*)d_in[1];
    const float* Wk = (const float*)d_in[2];
    const float* Wv = (const float*)d_in[3];
    const float* Wo = (const float*)d_in[4];
    const float* lq1 = (const float*)d_in[5];
    const float* lk1 = (const float*)d_in[6];
    const float* lq2 = (const float*)d_in[7];
    const float* lk2 = (const float*)d_in[8];
    const float* gw = (const float*)d_in[9];
    float* out = (float*)d_out;

    float *pQ, *pK, *pV, *pO, *pC, *pXr, *pWr;
    cudaGetSymbolAddress((void**)&pQ, g_Q);
    cudaGetSymbolAddress((void**)&pK, g_K);
    cudaGetSymbolAddress((void**)&pV, g_V);
    cudaGetSymbolAddress((void**)&pO, g_O);
    cudaGetSymbolAddress((void**)&pC, g_ctx);
    cudaGetSymbolAddress((void**)&pXr, g_Xr);
    cudaGetSymbolAddress((void**)&pWr, g_Wr);

    cudaFuncSetAttribute(gemm_tf32mma, cudaFuncAttributeMaxDynamicSharedMemorySize, GSMEM_BYTES);
    cudaFuncSetAttribute(flash_mma, cudaFuncAttributeMaxDynamicSharedMemorySize, FSMEM_BYTES);

    const dim3 ggrid(Ec / 128, MTOT / 128);
    const int NW4 = (Ec * Ec) / 4;            // weight float4 count
    const int NX4 = (MTOT * Ec) / 4;          // activation float4 count
    const int RB = 256;

    // round query once
    round_tf32_kernel<<<(NX4 + RB - 1) / RB, RB>>>(query, pXr, NX4);

    // Q/K/V projections (W rounded into reused buffer; stream-ordered reuse is safe)
    round_tf32_kernel<<<(NW4 + RB - 1) / RB, RB>>>(Wq, pWr, NW4);
    gemm_tf32mma<<<ggrid, 256, GSMEM_BYTES>>>(pXr, pWr, pQ, MTOT, Ec, Ec, 0.125f, 1);
    round_tf32_kernel<<<(NW4 + RB - 1) / RB, RB>>>(Wk, pWr, NW4);
    gemm_tf32mma<<<ggrid, 256, GSMEM_BYTES>>>(pXr, pWr, pK, MTOT, Ec, Ec, 1.0f, 1);
    round_tf32_kernel<<<(NW4 + RB - 1) / RB, RB>>>(Wv, pWr, NW4);
    gemm_tf32mma<<<ggrid, 256, GSMEM_BYTES>>>(pXr, pWr, pV, MTOT, Ec, Ec, 1.0f, 1);

    lambda_kernel<<<1, 1>>>(lq1, lk1, lq2, lk2);

    flash_mma<<<dim3(Tc / 64, 2 * Hc, Bc), 256, FSMEM_BYTES>>>(pQ, pK, pV, pO);

    combine_kernel<<<Bc * Hc * Tc, 128>>>(pO, gw, pC);

    // output projection (full fp32 out)
    round_tf32_kernel<<<(NW4 + RB - 1) / RB, RB>>>(Wo, pWr, NW4);
    gemm_tf32mma<<<ggrid, 256, GSMEM_BYTES>>>(pC, pWr, out, MTOT, Ec, Ec, 1.0f, 0);
}

// round 6
// speedup vs baseline: 3.4143x; 1.1161x over previous
#include <cuda_runtime.h>
#include <cstdint>
#include <math.h>

// Problem constants
#define Bc 2
#define Tc 2048
#define Ec 2048
#define Hc 16
#define Dc 64
#define MTOT (Bc * Tc)  // 4096

// ---------------------------------------------------------------------------
// Device scratch (no allocations allowed)
// ---------------------------------------------------------------------------
__device__ float g_Q[Bc * Tc * Ec];                       // tf32-rounded, pre-scaled
__device__ float g_K[Bc * Tc * Ec];                       // tf32-rounded
__device__ float g_V[Bc * Tc * Ec];                       // tf32-rounded
__device__ float g_O[(size_t)Bc * 2 * Hc * Tc * 2 * Dc];  // [B, 2H, T, 128]
__device__ float g_ctx[Bc * Tc * Ec];                     // tf32-rounded
__device__ float g_Xr[MTOT * Ec];                         // rounded query
__device__ float g_Wr[Ec * Ec];                           // rounded weight (reused serially)
__device__ float g_lam;

// ---------------------------------------------------------------------------
// PTX helpers
// ---------------------------------------------------------------------------
__device__ __forceinline__ uint32_t smem_u32(const void* p) {
    uint32_t a;
    asm("{ .reg .u64 t; cvta.to.shared.u64 t, %1; cvt.u32.u64 %0, t; }" : "=r"(a) : "l"(p));
    return a;
}
__device__ __forceinline__ void cpa16(uint32_t saddr, const void* g) {
    asm volatile("cp.async.cg.shared.global [%0], [%1], 16;" :: "r"(saddr), "l"(g));
}
#define CP_COMMIT() asm volatile("cp.async.commit_group;" ::: "memory")
#define CP_WAIT(n) asm volatile("cp.async.wait_group %0;" :: "n"(n) : "memory")

__device__ __forceinline__ uint32_t cvt_tf32(float f) {
    uint32_t r;
    asm("cvt.rna.tf32.f32 %0, %1;" : "=r"(r) : "f"(f));
    return r;
}
__device__ __forceinline__ float round_tf32f(float f) {
    return __uint_as_float(cvt_tf32(f));
}
__device__ __forceinline__ void mma_tf32(float* d, const uint32_t* a, const uint32_t* b) {
    asm volatile(
        "mma.sync.aligned.m16n8k8.row.col.f32.tf32.tf32.f32 "
        "{%0,%1,%2,%3}, {%4,%5,%6,%7}, {%8,%9}, {%0,%1,%2,%3};"
        : "+f"(d[0]), "+f"(d[1]), "+f"(d[2]), "+f"(d[3])
        : "r"(a[0]), "r"(a[1]), "r"(a[2]), "r"(a[3]), "r"(b[0]), "r"(b[1]));
}
// ldmatrix x4: four 8-row x 16-byte matrices; tf32 = pairs of b16 (bit-exact copy).
#define LDSM_X4(r, addr) \
    asm volatile("ldmatrix.sync.aligned.m8n8.x4.shared.b16 {%0,%1,%2,%3}, [%4];" \
                 : "=r"((r)[0]), "=r"((r)[1]), "=r"((r)[2]), "=r"((r)[3]) : "r"(addr))

// ---------------------------------------------------------------------------
// Round a buffer to tf32 values (rna), 1:1 copy.
// ---------------------------------------------------------------------------
__global__ __launch_bounds__(256) void round_tf32_kernel(
    const float* __restrict__ in, float* __restrict__ out, int n4)
{
    const int i = blockIdx.x * 256 + threadIdx.x;
    if (i < n4) {
        float4 v = *(const float4*)(in + 4 * (size_t)i);
        v.x = round_tf32f(v.x);
        v.y = round_tf32f(v.y);
        v.z = round_tf32f(v.z);
        v.w = round_tf32f(v.w);
        *(float4*)(out + 4 * (size_t)i) = v;
    }
}

// ---------------------------------------------------------------------------
// TF32 tensor-core GEMM: C[m,n] = alpha * sum_k X[m,k] * W[n,k]  (X @ W^T)
// Inputs pre-rounded to tf32. CTA 128x128, BK=32, 8 warps (2x4), warp 64x32.
// 3-stage cp.async, ONE barrier per K-tile, ldmatrix fragment loads.
// ---------------------------------------------------------------------------
#define BM 128
#define BN 128
#define BK 32
#define LDA 36
#define STAGE_FLOATS (BM * LDA)                 // 4608 floats per matrix
#define GSMEM_BYTES (3 * 2 * STAGE_FLOATS * 4)  // 110592 B

__device__ __forceinline__ void g_stage_load(float* stage, const float* __restrict__ X,
                                             const float* __restrict__ W,
                                             int m0, int n0, int K, int kt, int tid) {
    float* Ad = stage;
    float* Bd = stage + STAGE_FLOATS;
    const int kcol = kt * BK;
#pragma unroll
    for (int i = 0; i < 4; i++) {
        const int c = tid + 256 * i;
        const int r = c >> 3, sg = c & 7;
        cpa16(smem_u32(Ad + r * LDA + sg * 4), X + (size_t)(m0 + r) * K + kcol + sg * 4);
        cpa16(smem_u32(Bd + r * LDA + sg * 4), W + (size_t)(n0 + r) * K + kcol + sg * 4);
    }
    CP_COMMIT();
}

__global__ __launch_bounds__(256) void gemm_tf32mma(
    const float* __restrict__ X, const float* __restrict__ W,
    float* __restrict__ C, int M, int N, int K, float alpha, int round_out)
{
    extern __shared__ __align__(16) float smem[];
    const int tid = threadIdx.x;
    const int wid = tid >> 5;
    const int lane = tid & 31;
    const int g = lane >> 2;     // 0..7
    const int tig = lane & 3;    // 0..3
    const int warp_m = (wid & 1) * 64;
    const int warp_n = (wid >> 1) * 32;
    const int m0 = blockIdx.y * BM;
    const int n0 = blockIdx.x * BN;
    const int NK = K / BK;

    // ldmatrix per-lane row/col mapping
    const int arow = lane & 15;                  // A: lanes 0-15 rows, 16-31 rows (col+4)
    const int acol = (lane >> 4) * 4;
    const int brow = (lane & 7) + ((lane >> 4) << 3);  // B: {m0:r0-7,c0}{m1:r0-7,c4}{m2:r8-15,c0}{m3:r8-15,c4}
    const int bcol = ((lane >> 3) & 1) * 4;

    const uint32_t sb = smem_u32(smem);
    const uint32_t a_lane_off = (uint32_t)(((warp_m + arow) * LDA + acol) * 4);
    const uint32_t b_lane_off = (uint32_t)((STAGE_FLOATS + (warp_n + brow) * LDA + bcol) * 4);

    float acc[4][4][4];
#pragma unroll
    for (int i = 0; i < 4; i++)
#pragma unroll
        for (int j = 0; j < 4; j++)
#pragma unroll
            for (int r = 0; r < 4; r++) acc[i][j][r] = 0.f;

    // prologue: stages 0,1 <- kt 0,1
    g_stage_load(smem, X, W, m0, n0, K, 0, tid);
    g_stage_load(smem + 2 * STAGE_FLOATS, X, W, m0, n0, K, 1, tid);

    for (int kt = 0; kt < NK; kt++) {
        const int p = kt % 3;
        if (kt + 2 < NK) CP_WAIT(1); else CP_WAIT(0);
        __syncthreads();
        // one barrier does double duty: publishes stage kt, and proves stage
        // (kt+2)%3's readers (iteration kt-1) are done -> safe to refill it.
        if (kt + 2 < NK)
            g_stage_load(smem + ((kt + 2) % 3) * 2 * STAGE_FLOATS, X, W, m0, n0, K, kt + 2, tid);

        const uint32_t abase = sb + (uint32_t)(p * 2 * STAGE_FLOATS * 4) + a_lane_off;
        const uint32_t bbase = sb + (uint32_t)(p * 2 * STAGE_FLOATS * 4) + b_lane_off;
#pragma unroll
        for (int kk = 0; kk < BK; kk += 8) {
            uint32_t afr[4][4], blo[4], bhi[4];
#pragma unroll
            for (int i = 0; i < 4; i++)
                LDSM_X4(afr[i], abase + (uint32_t)((i * 16 * LDA + kk) * 4));
            LDSM_X4(blo, bbase + (uint32_t)(kk * 4));                    // j=0,1
            LDSM_X4(bhi, bbase + (uint32_t)((16 * LDA + kk) * 4));       // j=2,3
            uint32_t bfr[4][2];
            bfr[0][0] = blo[0]; bfr[0][1] = blo[1];
            bfr[1][0] = blo[2]; bfr[1][1] = blo[3];
            bfr[2][0] = bhi[0]; bfr[2][1] = bhi[1];
            bfr[3][0] = bhi[2]; bfr[3][1] = bhi[3];
#pragma unroll
            for (int i = 0; i < 4; i++)
#pragma unroll
                for (int j = 0; j < 4; j++)
                    mma_tf32(acc[i][j], afr[i], bfr[j]);
        }
    }

#pragma unroll
    for (int i = 0; i < 4; i++) {
#pragma unroll
        for (int j = 0; j < 4; j++) {
            const int row = m0 + warp_m + i * 16 + g;
            const int col = n0 + warp_n + j * 8 + 2 * tig;
            float2 v0, v1;
            v0.x = acc[i][j][0] * alpha; v0.y = acc[i][j][1] * alpha;
            v1.x = acc[i][j][2] * alpha; v1.y = acc[i][j][3] * alpha;
            if (round_out) {
                v0.x = round_tf32f(v0.x); v0.y = round_tf32f(v0.y);
                v1.x = round_tf32f(v1.x); v1.y = round_tf32f(v1.y);
            }
            *(float2*)(C + (size_t)row * N + col) = v0;
            *(float2*)(C + (size_t)(row + 8) * N + col) = v1;
        }
    }
}

// ---------------------------------------------------------------------------
// Lambda scalar
// ---------------------------------------------------------------------------
__global__ void lambda_kernel(const float* __restrict__ lq1, const float* __restrict__ lk1,
                              const float* __restrict__ lq2, const float* __restrict__ lk2)
{
    float s1 = 0.f, s2 = 0.f;
    for (int i = 0; i < Dc; i++) {
        s1 += lq1[i] * lk1[i];
        s2 += lq2[i] * lk2[i];
    }
    const float LI = 0.8f - 0.6f * expf(-3.6f);
    g_lam = expf(s1) - expf(s2) + LI;
}

// ---------------------------------------------------------------------------
// Tensorized causal flash attention. Inputs tf32-rounded -> raw-bit fragments.
// Grid (T/64, 2H, B), 256 threads (8 warps). ldmatrix for K (B-type) and P (A-type).
// ---------------------------------------------------------------------------
#define FLDA 68
#define FVLD 136
#define FSMEM_FLOATS (3 * 64 * FLDA + 64 * FVLD + 512)
#define FSMEM_BYTES (FSMEM_FLOATS * 4)   // 89088

__global__ __launch_bounds__(256) void flash_mma(
    const float* __restrict__ Q, const float* __restrict__ Km,
    const float* __restrict__ Vm, float* __restrict__ O)
{
    extern __shared__ float sm[];
    float* Qs = sm;                      // 64*68
    float* Ks = Qs + 64 * FLDA;
    float* Ss = Ks + 64 * FLDA;
    float* Vs = Ss + 64 * FLDA;          // 64*136
    float* redm = Vs + 64 * FVLD;        // 4*64
    float* reds = redm + 256;            // 4*64

    const int qtile = blockIdx.x;
    const int h2 = blockIdx.y;
    const int b = blockIdx.z;
    const int tid = threadIdx.x;
    const int wid = tid >> 5;
    const int lane = tid & 31;
    const int g = lane >> 2;   // 0..7
    const int tig = lane & 3;  // 0..3
    const int wq = (wid & 1) * 32;
    const int wk = (wid >> 1) * 16;
    const int wv = (wid >> 1) * 32;
    const int wn = wid >> 1;
    const int qm0 = qtile * 64;
    const int qoff = h2 * 64;
    const int voff = (h2 >> 1) * 128;

    // ldmatrix lane mappings
    const int arow = lane & 15;
    const int acol = (lane >> 4) * 4;
    const int brow = (lane & 7) + ((lane >> 4) << 3);
    const int bcol = ((lane >> 3) & 1) * 4;
    const uint32_t ks_base = smem_u32(Ks) + (uint32_t)(((wk + brow) * FLDA + bcol) * 4);
    const uint32_t ss_base = smem_u32(Ss) + (uint32_t)(((wq + arow) * FLDA + acol) * 4);

    // ---- load Q tile (row-major, padded) ----
    {
        const int r = tid >> 2, q4 = tid & 3;
        const float* Qrow = Q + (size_t)(b * Tc + qm0 + r) * Ec + qoff;
#pragma unroll
        for (int j = 0; j < 4; j++)
            *(float4*)(Qs + r * FLDA + q4 * 16 + j * 4) = *(const float4*)(Qrow + q4 * 16 + j * 4);
    }
    __syncthreads();

    // ---- Q fragments in registers (raw bits; already tf32-rounded) ----
    uint32_t qfr[2][8][4];
#pragma unroll
    for (int i = 0; i < 2; i++) {
        const uint32_t qb = smem_u32(Qs) + (uint32_t)(((wq + i * 16 + arow) * FLDA + acol) * 4);
#pragma unroll
        for (int kd = 0; kd < 8; kd++)
            LDSM_X4(qfr[i][kd], qb + (uint32_t)(kd * 8 * 4));
    }

    float oacc[2][4][4];
#pragma unroll
    for (int i = 0; i < 2; i++)
#pragma unroll
        for (int j = 0; j < 4; j++)
#pragma unroll
            for (int r = 0; r < 4; r++) oacc[i][j][r] = 0.f;
    float mrow[4] = {-1e30f, -1e30f, -1e30f, -1e30f};  // [i*2 + half]
    float lrow[4] = {0.f, 0.f, 0.f, 0.f};

    for (int kt = 0; kt <= qtile; kt++) {
        __syncthreads();

        // ---- load K, V tiles ----
        {
            const int r = tid >> 2, q4 = tid & 3;
            const float* Krow = Km + (size_t)(b * Tc + kt * 64 + r) * Ec + qoff;
#pragma unroll
            for (int j = 0; j < 4; j++)
                *(float4*)(Ks + r * FLDA + q4 * 16 + j * 4) = *(const float4*)(Krow + q4 * 16 + j * 4);
            const float* Vrow = Vm + (size_t)(b * Tc + kt * 64 + r) * Ec + voff;
#pragma unroll
            for (int j = 0; j < 8; j++)
                *(float4*)(Vs + r * FVLD + q4 * 4 + j * 16) = *(const float4*)(Vrow + q4 * 4 + j * 16);
        }
        __syncthreads();

        // ---- S = Q @ K^T (tf32 mma; K frags via ldmatrix) ----
        float sacc[2][2][4];
#pragma unroll
        for (int i = 0; i < 2; i++)
#pragma unroll
            for (int j = 0; j < 2; j++)
#pragma unroll
                for (int r = 0; r < 4; r++) sacc[i][j][r] = 0.f;
#pragma unroll
        for (int kd = 0; kd < 8; kd++) {
            uint32_t bl[4];
            LDSM_X4(bl, ks_base + (uint32_t)(kd * 8 * 4));   // j0: {bl0,bl1}, j1: {bl2,bl3}
            uint32_t bfr[2][2];
            bfr[0][0] = bl[0]; bfr[0][1] = bl[1];
            bfr[1][0] = bl[2]; bfr[1][1] = bl[3];
#pragma unroll
            for (int i = 0; i < 2; i++)
#pragma unroll
                for (int j = 0; j < 2; j++)
                    mma_tf32(sacc[i][j], qfr[i][kd], bfr[j]);
        }

        // ---- causal mask (diagonal tile only) ----
        if (kt == qtile) {
#pragma unroll
            for (int i = 0; i < 2; i++)
#pragma unroll
                for (int j = 0; j < 2; j++) {
                    const int colb = wk + j * 8 + 2 * tig;
                    const int row0 = wq + i * 16 + g;
                    if (colb > row0) sacc[i][j][0] = -1e30f;
                    if (colb + 1 > row0) sacc[i][j][1] = -1e30f;
                    if (colb > row0 + 8) sacc[i][j][2] = -1e30f;
                    if (colb + 1 > row0 + 8) sacc[i][j][3] = -1e30f;
                }
        }

        // ---- warp-slice row max over (j, tig) ----
#pragma unroll
        for (int i = 0; i < 2; i++) {
            float m0 = fmaxf(fmaxf(sacc[i][0][0], sacc[i][0][1]), fmaxf(sacc[i][1][0], sacc[i][1][1]));
            float m1 = fmaxf(fmaxf(sacc[i][0][2], sacc[i][0][3]), fmaxf(sacc[i][1][2], sacc[i][1][3]));
#pragma unroll
            for (int off = 1; off <= 2; off <<= 1) {
                m0 = fmaxf(m0, __shfl_xor_sync(0xffffffffu, m0, off));
                m1 = fmaxf(m1, __shfl_xor_sync(0xffffffffu, m1, off));
            }
            if (tig == 0) {
                redm[wn * 64 + wq + i * 16 + g] = m0;
                redm[wn * 64 + wq + i * 16 + 8 + g] = m1;
            }
        }
        __syncthreads();

        // ---- combine max across 4 n-warps; rescale factors ----
        float al[4];
#pragma unroll
        for (int i = 0; i < 2; i++)
#pragma unroll
            for (int h = 0; h < 2; h++) {
                const int r = wq + i * 16 + h * 8 + g;
                const float tm = fmaxf(fmaxf(redm[r], redm[64 + r]),
                                       fmaxf(redm[128 + r], redm[192 + r]));
                const int si = i * 2 + h;
                const float mnew = fmaxf(mrow[si], tm);
                al[si] = __expf(mrow[si] - mnew);
                mrow[si] = mnew;
            }

        // ---- exp, store tf32-rounded P to smem, slice sums ----
#pragma unroll
        for (int i = 0; i < 2; i++) {
            float s0 = 0.f, s1 = 0.f;
            const int r0 = wq + i * 16 + g;
#pragma unroll
            for (int j = 0; j < 2; j++) {
                const int col = wk + j * 8 + 2 * tig;
                const float p00 = __expf(sacc[i][j][0] - mrow[i * 2]);
                const float p01 = __expf(sacc[i][j][1] - mrow[i * 2]);
                const float p10 = __expf(sacc[i][j][2] - mrow[i * 2 + 1]);
                const float p11 = __expf(sacc[i][j][3] - mrow[i * 2 + 1]);
                s0 += p00 + p01;
                s1 += p10 + p11;
                *(float2*)(Ss + r0 * FLDA + col) =
                    make_float2(round_tf32f(p00), round_tf32f(p01));
                *(float2*)(Ss + (r0 + 8) * FLDA + col) =
                    make_float2(round_tf32f(p10), round_tf32f(p11));
            }
#pragma unroll
            for (int off = 1; off <= 2; off <<= 1) {
                s0 += __shfl_xor_sync(0xffffffffu, s0, off);
                s1 += __shfl_xor_sync(0xffffffffu, s1, off);
            }
            if (tig == 0) {
                reds[wn * 64 + wq + i * 16 + g] = s0;
                reds[wn * 64 + wq + i * 16 + 8 + g] = s1;
            }
        }
        __syncthreads();

        // ---- total sums; update l; rescale O accumulators ----
#pragma unroll
        for (int i = 0; i < 2; i++)
#pragma unroll
            for (int h = 0; h < 2; h++) {
                const int r = wq + i * 16 + h * 8 + g;
                const float ts = reds[r] + reds[64 + r] + reds[128 + r] + reds[192 + r];
                const int si = i * 2 + h;
                lrow[si] = lrow[si] * al[si] + ts;
            }
#pragma unroll
        for (int i = 0; i < 2; i++)
#pragma unroll
            for (int jv = 0; jv < 4; jv++) {
                oacc[i][jv][0] *= al[i * 2];
                oacc[i][jv][1] *= al[i * 2];
                oacc[i][jv][2] *= al[i * 2 + 1];
                oacc[i][jv][3] *= al[i * 2 + 1];
            }

        // ---- O += P @ V (tf32 mma; P frags via ldmatrix, V scalar) ----
#pragma unroll
        for (int kn = 0; kn < 8; kn++) {
            uint32_t afr[2][4];
#pragma unroll
            for (int i = 0; i < 2; i++)
                LDSM_X4(afr[i], ss_base + (uint32_t)((i * 16 * FLDA + kn * 8) * 4));
#pragma unroll
            for (int jv = 0; jv < 4; jv++) {
                uint32_t bfr[2];
                const uint32_t* bp = (const uint32_t*)(Vs + (kn * 8 + tig) * FVLD + wv + jv * 8 + g);
                bfr[0] = bp[0];
                bfr[1] = bp[4 * FVLD];
#pragma unroll
                for (int i = 0; i < 2; i++)
                    mma_tf32(oacc[i][jv], afr[i], bfr);
            }
        }
    }

    // ---- epilogue ----
#pragma unroll
    for (int i = 0; i < 2; i++) {
        const float inv0 = 1.f / lrow[i * 2];
        const float inv1 = 1.f / lrow[i * 2 + 1];
        const int r0 = wq + i * 16 + g;
#pragma unroll
        for (int jv = 0; jv < 4; jv++) {
            const int col = wv + jv * 8 + 2 * tig;
            float* d0 = O + ((size_t)(b * 2 * Hc + h2) * Tc + qm0 + r0) * 128 + col;
            float* d1 = O + ((size_t)(b * 2 * Hc + h2) * Tc + qm0 + r0 + 8) * 128 + col;
            *(float2*)d0 = make_float2(oacc[i][jv][0] * inv0, oacc[i][jv][1] * inv0);
            *(float2*)d1 = make_float2(oacc[i][jv][2] * inv1, oacc[i][jv][3] * inv1);
        }
    }
}

// ---------------------------------------------------------------------------
// Combine: x = O[2h] - lam*O[2h+1]; RMSNorm over 128; * g * (1-LI)
// Output rounded to tf32 (consumed by tensor-core GEMM).
// ---------------------------------------------------------------------------
__global__ __launch_bounds__(128) void combine_kernel(
    const float* __restrict__ O, const float* __restrict__ g,
    float* __restrict__ ctx)
{
    const int idx = blockIdx.x;
    const int t = idx % Tc;
    const int h = (idx / Tc) % Hc;
    const int b = idx / (Tc * Hc);
    const int e = threadIdx.x;

    const size_t base1 = ((size_t)(b * 2 * Hc + 2 * h) * Tc + t) * 128;
    const size_t base2 = base1 + (size_t)Tc * 128;

    const float lam = g_lam;
    const float x = O[base1 + e] - lam * O[base2 + e];

    float v = x * x;
#pragma unroll
    for (int off = 16; off > 0; off >>= 1)
        v += __shfl_xor_sync(0xffffffffu, v, off, 32);

    __shared__ float red[4];
    if ((threadIdx.x & 31) == 0) red[threadIdx.x >> 5] = v;
    __syncthreads();
    const float tot = red[0] + red[1] + red[2] + red[3];
    const float rms = rsqrtf(tot * (1.f / 128.f) + 1e-5f);

    const float LI = 0.8f - 0.6f * expf(-3.6f);
    ctx[(size_t)(b * Tc + t) * Ec + h * 128 + e] =
        round_tf32f(x * rms * g[e] * (1.f - LI));
}

// ---------------------------------------------------------------------------
// Host launcher
// ---------------------------------------------------------------------------
extern "C" void kernel_launch(void* const* d_in, const int* in_sizes, int n_in,
                              void* d_out, int out_size)
{
    (void)in_sizes; (void)n_in; (void)out_size;

    const float* query = (const float*)d_in[0];
    const float* Wq = (const float*)d_in[1];
    const float* Wk = (const float*)d_in[2];
    const float* Wv = (const float*)d_in[3];
    const float* Wo = (const float*)d_in[4];
    const float* lq1 = (const float*)d_in[5];
    const float* lk1 = (const float*)d_in[6];
    const float* lq2 = (const float*)d_in[7];
    const float* lk2 = (const float*)d_in[8];
    const float* gw = (const float*)d_in[9];
    float* out = (float*)d_out;

    float *pQ, *pK, *pV, *pO, *pC, *pXr, *pWr;
    cudaGetSymbolAddress((void**)&pQ, g_Q);
    cudaGetSymbolAddress((void**)&pK, g_K);
    cudaGetSymbolAddress((void**)&pV, g_V);
    cudaGetSymbolAddress((void**)&pO, g_O);
    cudaGetSymbolAddress((void**)&pC, g_ctx);
    cudaGetSymbolAddress((void**)&pXr, g_Xr);
    cudaGetSymbolAddress((void**)&pWr, g_Wr);

    cudaFuncSetAttribute(gemm_tf32mma, cudaFuncAttributeMaxDynamicSharedMemorySize, GSMEM_BYTES);
    cudaFuncSetAttribute(flash_mma, cudaFuncAttributeMaxDynamicSharedMemorySize, FSMEM_BYTES);

    const dim3 ggrid(Ec / 128, MTOT / 128);
    const int NW4 = (Ec * Ec) / 4;
    const int NX4 = (MTOT * Ec) / 4;
    const int RB = 256;

    // round query once
    round_tf32_kernel<<<(NX4 + RB - 1) / RB, RB>>>(query, pXr, NX4);

    // Q/K/V projections (W rounded into reused buffer; stream-ordered reuse safe)
    round_tf32_kernel<<<(NW4 + RB - 1) / RB, RB>>>(Wq, pWr, NW4);
    gemm_tf32mma<<<ggrid, 256, GSMEM_BYTES>>>(pXr, pWr, pQ, MTOT, Ec, Ec, 0.125f, 1);
    round_tf32_kernel<<<(NW4 + RB - 1) / RB, RB>>>(Wk, pWr, NW4);
    gemm_tf32mma<<<ggrid, 256, GSMEM_BYTES>>>(pXr, pWr, pK, MTOT, Ec, Ec, 1.0f, 1);
    round_tf32_kernel<<<(NW4 + RB - 1) / RB, RB>>>(Wv, pWr, NW4);
    gemm_tf32mma<<<ggrid, 256, GSMEM_BYTES>>>(pXr, pWr, pV, MTOT, Ec, Ec, 1.0f, 1);

    lambda_kernel<<<1, 1>>>(lq1, lk1, lq2, lk2);

    flash_mma<<<dim3(Tc / 64, 2 * Hc, Bc), 256, FSMEM_BYTES>>>(pQ, pK, pV, pO);

    combine_kernel<<<Bc * Hc * Tc, 128>>>(pO, gw, pC);

    // output projection (full fp32 out)
    round_tf32_kernel<<<(NW4 + RB - 1) / RB, RB>>>(Wo, pWr, NW4);
    gemm_tf32mma<<<ggrid, 256, GSMEM_BYTES>>>(pC, pWr, out, MTOT, Ec, Ec, 1.0f, 0);
}

// round 7
// speedup vs baseline: 6.2529x; 1.8314x over previous
#include <cuda_runtime.h>
#include <cuda_fp16.h>
#include <cstdint>
#include <math.h>

// Problem constants
#define Bc 2
#define Tc 2048
#define Ec 2048
#define Hc 16
#define Dc 64
#define MTOT (Bc * Tc)  // 4096

// ---------------------------------------------------------------------------
// Device scratch (no allocations allowed)
// ---------------------------------------------------------------------------
__device__ __half g_Q[Bc * Tc * Ec];                      // fp16, pre-scaled
__device__ __half g_K[Bc * Tc * Ec];                      // fp16
__device__ __half g_V[Bc * Tc * Ec];                      // fp16
__device__ float  g_O[(size_t)Bc * 2 * Hc * Tc * 2 * Dc]; // [B, 2H, T, 128] fp32
__device__ __half g_ctx[Bc * Tc * Ec];                    // fp16
__device__ __half g_Xh[MTOT * Ec];                        // fp16 query
__device__ __half g_Wh[Ec * Ec];                          // fp16 weight (reused serially)
__device__ float  g_lam;

// ---------------------------------------------------------------------------
// PTX helpers
// ---------------------------------------------------------------------------
__device__ __forceinline__ uint32_t smem_u32(const void* p) {
    uint32_t a;
    asm("{ .reg .u64 t; cvta.to.shared.u64 t, %1; cvt.u32.u64 %0, t; }" : "=r"(a) : "l"(p));
    return a;
}
__device__ __forceinline__ void cpa16(uint32_t saddr, const void* g) {
    asm volatile("cp.async.cg.shared.global [%0], [%1], 16;" :: "r"(saddr), "l"(g));
}
#define CP_COMMIT() asm volatile("cp.async.commit_group;" ::: "memory")
#define CP_WAIT(n) asm volatile("cp.async.wait_group %0;" :: "n"(n) : "memory")

__device__ __forceinline__ void mma_f16(float* d, const uint32_t* a, const uint32_t* b) {
    asm volatile(
        "mma.sync.aligned.m16n8k16.row.col.f32.f16.f16.f32 "
        "{%0,%1,%2,%3}, {%4,%5,%6,%7}, {%8,%9}, {%0,%1,%2,%3};"
        : "+f"(d[0]), "+f"(d[1]), "+f"(d[2]), "+f"(d[3])
        : "r"(a[0]), "r"(a[1]), "r"(a[2]), "r"(a[3]), "r"(b[0]), "r"(b[1]));
}
#define LDSM_X4(r, addr) \
    asm volatile("ldmatrix.sync.aligned.m8n8.x4.shared.b16 {%0,%1,%2,%3}, [%4];" \
                 : "=r"((r)[0]), "=r"((r)[1]), "=r"((r)[2]), "=r"((r)[3]) : "r"(addr))
#define LDSM_X4_T(r, addr) \
    asm volatile("ldmatrix.sync.aligned.m8n8.x4.trans.shared.b16 {%0,%1,%2,%3}, [%4];" \
                 : "=r"((r)[0]), "=r"((r)[1]), "=r"((r)[2]), "=r"((r)[3]) : "r"(addr))

// ---------------------------------------------------------------------------
// fp32 -> fp16 convert (1:1)
// ---------------------------------------------------------------------------
__global__ __launch_bounds__(256) void cvt_f2h_kernel(
    const float* __restrict__ in, __half* __restrict__ out, int n4)
{
    const int i = blockIdx.x * 256 + threadIdx.x;
    if (i < n4) {
        float4 v = *(const float4*)(in + 4 * (size_t)i);
        __half2* o = (__half2*)(out + 4 * (size_t)i);
        o[0] = __floats2half2_rn(v.x, v.y);
        o[1] = __floats2half2_rn(v.z, v.w);
    }
}

// ---------------------------------------------------------------------------
// FP16 tensor-core GEMM: C[m,n] = alpha * sum_k X[m,k] * W[n,k]  (X @ W^T)
// CTA 128x128, BK=32, 8 warps (2x4), warp 64x32, m16n8k16, fp32 accum.
// 3-stage cp.async, one barrier per K-tile, ldmatrix fragments.
// smem row stride 40 halfs (80B): ldmatrix row addrs mod 128B all distinct.
// ---------------------------------------------------------------------------
#define BM 128
#define BN 128
#define BK 32
#define HLDA 40
#define STAGE_H (BM * HLDA)                      // 5120 halfs per matrix
#define GSMEM_BYTES (3 * 2 * STAGE_H * 2)        // 61440 B

__device__ __forceinline__ void g_stage_load(__half* stage, const __half* __restrict__ X,
                                             const __half* __restrict__ W,
                                             int m0, int n0, int K, int kt, int tid) {
    __half* Ad = stage;
    __half* Bd = stage + STAGE_H;
    const int kcol = kt * BK;
#pragma unroll
    for (int i = 0; i < 2; i++) {
        const int c = tid + 256 * i;          // 0..511
        const int r = c >> 2, sg = c & 3;     // row 0..127, 16B seg 0..3
        cpa16(smem_u32(Ad + r * HLDA + sg * 8), X + (size_t)(m0 + r) * K + kcol + sg * 8);
        cpa16(smem_u32(Bd + r * HLDA + sg * 8), W + (size_t)(n0 + r) * K + kcol + sg * 8);
    }
    CP_COMMIT();
}

__global__ __launch_bounds__(256) void gemm_f16mma(
    const __half* __restrict__ X, const __half* __restrict__ W,
    float* __restrict__ Cf, __half* __restrict__ Ch,
    int M, int N, int K, float alpha, int out_half)
{
    extern __shared__ __align__(16) __half smem[];
    const int tid = threadIdx.x;
    const int wid = tid >> 5;
    const int lane = tid & 31;
    const int g = lane >> 2;
    const int tig = lane & 3;
    const int warp_m = (wid & 1) * 64;
    const int warp_n = (wid >> 1) * 32;
    const int m0 = blockIdx.y * BM;
    const int n0 = blockIdx.x * BN;
    const int NK = K / BK;

    const uint32_t sb = smem_u32(smem);
    // A: lanes 0-15 rows, lanes 16-31 same rows at k-bytes +16
    const uint32_t a_off = (uint32_t)(((warp_m + (lane & 15)) * HLDA + (lane >> 4) * 8) * 2);
    // B: {j0 rows k0}{j0 rows k8}{j1 rows k0}{j1 rows k8}
    const uint32_t b_off = (uint32_t)((STAGE_H + (warp_n + (lane & 7) + ((lane >> 4) << 3)) * HLDA
                                      + ((lane >> 3) & 1) * 8) * 2);

    float acc[4][4][4];
#pragma unroll
    for (int i = 0; i < 4; i++)
#pragma unroll
        for (int j = 0; j < 4; j++)
#pragma unroll
            for (int r = 0; r < 4; r++) acc[i][j][r] = 0.f;

    g_stage_load(smem, X, W, m0, n0, K, 0, tid);
    g_stage_load(smem + 2 * STAGE_H, X, W, m0, n0, K, 1, tid);

    for (int kt = 0; kt < NK; kt++) {
        const int p = kt % 3;
        if (kt + 2 < NK) CP_WAIT(1); else CP_WAIT(0);
        __syncthreads();
        if (kt + 2 < NK)
            g_stage_load(smem + ((kt + 2) % 3) * 2 * STAGE_H, X, W, m0, n0, K, kt + 2, tid);

        const uint32_t stg = sb + (uint32_t)(p * 2 * STAGE_H * 2);
#pragma unroll
        for (int kc = 0; kc < 2; kc++) {              // two k16 chunks in BK=32
            const uint32_t ko = (uint32_t)(kc * 32);  // 16 halfs = 32B
            uint32_t afr[4][4], b0[4], b1[4];
#pragma unroll
            for (int i = 0; i < 4; i++)
                LDSM_X4(afr[i], stg + a_off + (uint32_t)(i * 16 * HLDA * 2) + ko);
            LDSM_X4(b0, stg + b_off + ko);                              // j=0,1
            LDSM_X4(b1, stg + b_off + (uint32_t)(16 * HLDA * 2) + ko);  // j=2,3
            uint32_t bfr[4][2];
            bfr[0][0] = b0[0]; bfr[0][1] = b0[1];
            bfr[1][0] = b0[2]; bfr[1][1] = b0[3];
            bfr[2][0] = b1[0]; bfr[2][1] = b1[1];
            bfr[3][0] = b1[2]; bfr[3][1] = b1[3];
#pragma unroll
            for (int i = 0; i < 4; i++)
#pragma unroll
                for (int j = 0; j < 4; j++)
                    mma_f16(acc[i][j], afr[i], bfr[j]);
        }
    }

#pragma unroll
    for (int i = 0; i < 4; i++) {
#pragma unroll
        for (int j = 0; j < 4; j++) {
            const int row = m0 + warp_m + i * 16 + g;
            const int col = n0 + warp_n + j * 8 + 2 * tig;
            const float c0 = acc[i][j][0] * alpha, c1 = acc[i][j][1] * alpha;
            const float c2 = acc[i][j][2] * alpha, c3 = acc[i][j][3] * alpha;
            if (out_half) {
                *(__half2*)(Ch + (size_t)row * N + col) = __floats2half2_rn(c0, c1);
                *(__half2*)(Ch + (size_t)(row + 8) * N + col) = __floats2half2_rn(c2, c3);
            } else {
                *(float2*)(Cf + (size_t)row * N + col) = make_float2(c0, c1);
                *(float2*)(Cf + (size_t)(row + 8) * N + col) = make_float2(c2, c3);
            }
        }
    }
}

// ---------------------------------------------------------------------------
// Lambda scalar
// ---------------------------------------------------------------------------
__global__ void lambda_kernel(const float* __restrict__ lq1, const float* __restrict__ lk1,
                              const float* __restrict__ lq2, const float* __restrict__ lk2)
{
    float s1 = 0.f, s2 = 0.f;
    for (int i = 0; i < Dc; i++) {
        s1 += lq1[i] * lk1[i];
        s2 += lq2[i] * lk2[i];
    }
    const float LI = 0.8f - 0.6f * expf(-3.6f);
    g_lam = expf(s1) - expf(s2) + LI;
}

// ---------------------------------------------------------------------------
// FP16 tensorized causal flash attention. Grid (T/64, 2H, B), 256 thr (8 warps).
// Q/K/P via ldmatrix; V via ldmatrix.trans. fp32 softmax + accumulators.
// smem (halfs): Qs[64][72], Ks[64][72], Ss[64][72], Vs[64][136]; + 512 floats red
// ---------------------------------------------------------------------------
#define FQLD 72
#define FVLD2 136
#define FH_TOTAL (3 * 64 * FQLD + 64 * FVLD2)            // 22528 halfs
#define FSMEM_BYTES (FH_TOTAL * 2 + 512 * 4)             // 47104 B

__global__ __launch_bounds__(256) void flash_f16(
    const __half* __restrict__ Q, const __half* __restrict__ Km,
    const __half* __restrict__ Vm, float* __restrict__ O)
{
    extern __shared__ __align__(16) __half smh[];
    __half* Qs = smh;                      // 64*72
    __half* Ks = Qs + 64 * FQLD;
    __half* Ss = Ks + 64 * FQLD;
    __half* Vs = Ss + 64 * FQLD;           // 64*136
    float* redm = (float*)(smh + FH_TOTAL);  // 4*64
    float* reds = redm + 256;                // 4*64

    const int qtile = blockIdx.x;
    const int h2 = blockIdx.y;
    const int b = blockIdx.z;
    const int tid = threadIdx.x;
    const int wid = tid >> 5;
    const int lane = tid & 31;
    const int g = lane >> 2;
    const int tig = lane & 3;
    const int wq = (wid & 1) * 32;
    const int wk = (wid >> 1) * 16;
    const int wv = (wid >> 1) * 32;
    const int wn = wid >> 1;
    const int qm0 = qtile * 64;
    const int qoff = h2 * 64;
    const int voff = (h2 >> 1) * 128;

    // fragment lane bases
    const uint32_t qa_off = (uint32_t)(((lane & 15) * FQLD + (lane >> 4) * 8) * 2);
    const uint32_t ks_base = smem_u32(Ks) +
        (uint32_t)(((wk + (lane & 7) + ((lane >> 4) << 3)) * FQLD + ((lane >> 3) & 1) * 8) * 2);
    const uint32_t ss_base = smem_u32(Ss) + (uint32_t)((wq * FQLD) * 2) + qa_off;
    const uint32_t vs_base = smem_u32(Vs) +
        (uint32_t)((((lane & 7) + ((lane >> 3) & 1) * 8) * FVLD2 + wv + ((lane >> 4) & 1) * 8) * 2);

    // ---- load Q tile ----
    {
        const int r = tid >> 3, sg = tid & 7;   // 32 rows per pass? 256 thr: r 0..31
#pragma unroll
        for (int it = 0; it < 2; it++) {
            const int row = r + it * 32;
            *(uint4*)(Qs + row * FQLD + sg * 8) =
                *(const uint4*)(Q + (size_t)(b * Tc + qm0 + row) * Ec + qoff + sg * 8);
        }
    }
    __syncthreads();

    // ---- Q fragments in registers ----
    uint32_t qfr[2][4][4];
#pragma unroll
    for (int i = 0; i < 2; i++) {
        const uint32_t qb = smem_u32(Qs) + (uint32_t)(((wq + i * 16) * FQLD) * 2) + qa_off;
#pragma unroll
        for (int kd = 0; kd < 4; kd++)
            LDSM_X4(qfr[i][kd], qb + (uint32_t)(kd * 32));
    }

    float oacc[2][4][4];
#pragma unroll
    for (int i = 0; i < 2; i++)
#pragma unroll
        for (int j = 0; j < 4; j++)
#pragma unroll
            for (int r = 0; r < 4; r++) oacc[i][j][r] = 0.f;
    float mrow[4] = {-1e30f, -1e30f, -1e30f, -1e30f};
    float lrow[4] = {0.f, 0.f, 0.f, 0.f};

    for (int kt = 0; kt <= qtile; kt++) {
        __syncthreads();

        // ---- load K, V tiles ----
        {
            const int r = tid >> 3, sg = tid & 7;
#pragma unroll
            for (int it = 0; it < 2; it++) {
                const int row = r + it * 32;
                *(uint4*)(Ks + row * FQLD + sg * 8) =
                    *(const uint4*)(Km + (size_t)(b * Tc + kt * 64 + row) * Ec + qoff + sg * 8);
            }
            const int vr = tid >> 4, vsg = tid & 15;
#pragma unroll
            for (int it = 0; it < 4; it++) {
                const int row = vr + it * 16;
                *(uint4*)(Vs + row * FVLD2 + vsg * 8) =
                    *(const uint4*)(Vm + (size_t)(b * Tc + kt * 64 + row) * Ec + voff + vsg * 8);
            }
        }
        __syncthreads();

        // ---- S = Q @ K^T ----
        float sacc[2][2][4];
#pragma unroll
        for (int i = 0; i < 2; i++)
#pragma unroll
            for (int j = 0; j < 2; j++)
#pragma unroll
                for (int r = 0; r < 4; r++) sacc[i][j][r] = 0.f;
#pragma unroll
        for (int kd = 0; kd < 4; kd++) {
            uint32_t bl[4];
            LDSM_X4(bl, ks_base + (uint32_t)(kd * 32));
            uint32_t bfr[2][2];
            bfr[0][0] = bl[0]; bfr[0][1] = bl[1];
            bfr[1][0] = bl[2]; bfr[1][1] = bl[3];
#pragma unroll
            for (int i = 0; i < 2; i++)
#pragma unroll
                for (int j = 0; j < 2; j++)
                    mma_f16(sacc[i][j], qfr[i][kd], bfr[j]);
        }

        // ---- causal mask (diagonal tile) ----
        if (kt == qtile) {
#pragma unroll
            for (int i = 0; i < 2; i++)
#pragma unroll
                for (int j = 0; j < 2; j++) {
                    const int colb = wk + j * 8 + 2 * tig;
                    const int row0 = wq + i * 16 + g;
                    if (colb > row0) sacc[i][j][0] = -1e30f;
                    if (colb + 1 > row0) sacc[i][j][1] = -1e30f;
                    if (colb > row0 + 8) sacc[i][j][2] = -1e30f;
                    if (colb + 1 > row0 + 8) sacc[i][j][3] = -1e30f;
                }
        }

        // ---- warp-slice row max ----
#pragma unroll
        for (int i = 0; i < 2; i++) {
            float m0 = fmaxf(fmaxf(sacc[i][0][0], sacc[i][0][1]), fmaxf(sacc[i][1][0], sacc[i][1][1]));
            float m1 = fmaxf(fmaxf(sacc[i][0][2], sacc[i][0][3]), fmaxf(sacc[i][1][2], sacc[i][1][3]));
#pragma unroll
            for (int off = 1; off <= 2; off <<= 1) {
                m0 = fmaxf(m0, __shfl_xor_sync(0xffffffffu, m0, off));
                m1 = fmaxf(m1, __shfl_xor_sync(0xffffffffu, m1, off));
            }
            if (tig == 0) {
                redm[wn * 64 + wq + i * 16 + g] = m0;
                redm[wn * 64 + wq + i * 16 + 8 + g] = m1;
            }
        }
        __syncthreads();

        // ---- combine max; rescale factors ----
        float al[4];
#pragma unroll
        for (int i = 0; i < 2; i++)
#pragma unroll
            for (int h = 0; h < 2; h++) {
                const int r = wq + i * 16 + h * 8 + g;
                const float tm = fmaxf(fmaxf(redm[r], redm[64 + r]),
                                       fmaxf(redm[128 + r], redm[192 + r]));
                const int si = i * 2 + h;
                const float mnew = fmaxf(mrow[si], tm);
                al[si] = __expf(mrow[si] - mnew);
                mrow[si] = mnew;
            }

        // ---- exp, store fp16 P, slice sums ----
#pragma unroll
        for (int i = 0; i < 2; i++) {
            float s0 = 0.f, s1 = 0.f;
            const int r0 = wq + i * 16 + g;
#pragma unroll
            for (int j = 0; j < 2; j++) {
                const int col = wk + j * 8 + 2 * tig;
                const float p00 = __expf(sacc[i][j][0] - mrow[i * 2]);
                const float p01 = __expf(sacc[i][j][1] - mrow[i * 2]);
                const float p10 = __expf(sacc[i][j][2] - mrow[i * 2 + 1]);
                const float p11 = __expf(sacc[i][j][3] - mrow[i * 2 + 1]);
                s0 += p00 + p01;
                s1 += p10 + p11;
                *(__half2*)(Ss + r0 * FQLD + col) = __floats2half2_rn(p00, p01);
                *(__half2*)(Ss + (r0 + 8) * FQLD + col) = __floats2half2_rn(p10, p11);
            }
#pragma unroll
            for (int off = 1; off <= 2; off <<= 1) {
                s0 += __shfl_xor_sync(0xffffffffu, s0, off);
                s1 += __shfl_xor_sync(0xffffffffu, s1, off);
            }
            if (tig == 0) {
                reds[wn * 64 + wq + i * 16 + g] = s0;
                reds[wn * 64 + wq + i * 16 + 8 + g] = s1;
            }
        }
        __syncthreads();

        // ---- update l; rescale O ----
#pragma unroll
        for (int i = 0; i < 2; i++)
#pragma unroll
            for (int h = 0; h < 2; h++) {
                const int r = wq + i * 16 + h * 8 + g;
                const float ts = reds[r] + reds[64 + r] + reds[128 + r] + reds[192 + r];
                const int si = i * 2 + h;
                lrow[si] = lrow[si] * al[si] + ts;
            }
#pragma unroll
        for (int i = 0; i < 2; i++)
#pragma unroll
            for (int jv = 0; jv < 4; jv++) {
                oacc[i][jv][0] *= al[i * 2];
                oacc[i][jv][1] *= al[i * 2];
                oacc[i][jv][2] *= al[i * 2 + 1];
                oacc[i][jv][3] *= al[i * 2 + 1];
            }

        // ---- O += P @ V (P via ldmatrix, V via ldmatrix.trans) ----
#pragma unroll
        for (int kn = 0; kn < 4; kn++) {            // 16-key chunks
            uint32_t afr[2][4];
#pragma unroll
            for (int i = 0; i < 2; i++)
                LDSM_X4(afr[i], ss_base + (uint32_t)((i * 16 * FQLD) * 2 + kn * 32));
#pragma unroll
            for (int jp = 0; jp < 2; jp++) {        // v col 16-blocks
                uint32_t vl[4];
                LDSM_X4_T(vl, vs_base + (uint32_t)((kn * 16 * FVLD2 + jp * 16) * 2));
                uint32_t bfr[2][2];
                bfr[0][0] = vl[0]; bfr[0][1] = vl[1];   // jv = 2*jp
                bfr[1][0] = vl[2]; bfr[1][1] = vl[3];   // jv = 2*jp+1
#pragma unroll
                for (int i = 0; i < 2; i++) {
                    mma_f16(oacc[i][2 * jp], afr[i], bfr[0]);
                    mma_f16(oacc[i][2 * jp + 1], afr[i], bfr[1]);
                }
            }
        }
    }

    // ---- epilogue ----
#pragma unroll
    for (int i = 0; i < 2; i++) {
        const float inv0 = 1.f / lrow[i * 2];
        const float inv1 = 1.f / lrow[i * 2 + 1];
        const int r0 = wq + i * 16 + g;
#pragma unroll
        for (int jv = 0; jv < 4; jv++) {
            const int col = wv + jv * 8 + 2 * tig;
            float* d0 = O + ((size_t)(b * 2 * Hc + h2) * Tc + qm0 + r0) * 128 + col;
            float* d1 = O + ((size_t)(b * 2 * Hc + h2) * Tc + qm0 + r0 + 8) * 128 + col;
            *(float2*)d0 = make_float2(oacc[i][jv][0] * inv0, oacc[i][jv][1] * inv0);
            *(float2*)d1 = make_float2(oacc[i][jv][2] * inv1, oacc[i][jv][3] * inv1);
        }
    }
}

// ---------------------------------------------------------------------------
// Combine: x = O[2h] - lam*O[2h+1]; RMSNorm over 128; * g * (1-LI); -> fp16 ctx
// ---------------------------------------------------------------------------
__global__ __launch_bounds__(128) void combine_kernel(
    const float* __restrict__ O, const float* __restrict__ g,
    __half* __restrict__ ctx)
{
    const int idx = blockIdx.x;
    const int t = idx % Tc;
    const int h = (idx / Tc) % Hc;
    const int b = idx / (Tc * Hc);
    const int e = threadIdx.x;

    const size_t base1 = ((size_t)(b * 2 * Hc + 2 * h) * Tc + t) * 128;
    const size_t base2 = base1 + (size_t)Tc * 128;

    const float lam = g_lam;
    const float x = O[base1 + e] - lam * O[base2 + e];

    float v = x * x;
#pragma unroll
    for (int off = 16; off > 0; off >>= 1)
        v += __shfl_xor_sync(0xffffffffu, v, off, 32);

    __shared__ float red[4];
    if ((threadIdx.x & 31) == 0) red[threadIdx.x >> 5] = v;
    __syncthreads();
    const float tot = red[0] + red[1] + red[2] + red[3];
    const float rms = rsqrtf(tot * (1.f / 128.f) + 1e-5f);

    const float LI = 0.8f - 0.6f * expf(-3.6f);
    ctx[(size_t)(b * Tc + t) * Ec + h * 128 + e] =
        __float2half_rn(x * rms * g[e] * (1.f - LI));
}

// ---------------------------------------------------------------------------
// Host launcher
// ---------------------------------------------------------------------------
extern "C" void kernel_launch(void* const* d_in, const int* in_sizes, int n_in,
                              void* d_out, int out_size)
{
    (void)in_sizes; (void)n_in; (void)out_size;

    const float* query = (const float*)d_in[0];
    const float* Wq = (const float*)d_in[1];
    const float* Wk = (const float*)d_in[2];
    const float* Wv = (const float*)d_in[3];
    const float* Wo = (const float*)d_in[4];
    const float* lq1 = (const float*)d_in[5];
    const float* lk1 = (const float*)d_in[6];
    const float* lq2 = (const float*)d_in[7];
    const float* lk2 = (const float*)d_in[8];
    const float* gw = (const float*)d_in[9];
    float* out = (float*)d_out;

    __half *pQ, *pK, *pV, *pC, *pXh, *pWh;
    float *pO;
    cudaGetSymbolAddress((void**)&pQ, g_Q);
    cudaGetSymbolAddress((void**)&pK, g_K);
    cudaGetSymbolAddress((void**)&pV, g_V);
    cudaGetSymbolAddress((void**)&pO, g_O);
    cudaGetSymbolAddress((void**)&pC, g_ctx);
    cudaGetSymbolAddress((void**)&pXh, g_Xh);
    cudaGetSymbolAddress((void**)&pWh, g_Wh);

    cudaFuncSetAttribute(gemm_f16mma, cudaFuncAttributeMaxDynamicSharedMemorySize, GSMEM_BYTES);
    cudaFuncSetAttribute(flash_f16, cudaFuncAttributeMaxDynamicSharedMemorySize, FSMEM_BYTES);

    const dim3 ggrid(Ec / 128, MTOT / 128);
    const int NW4 = (Ec * Ec) / 4;
    const int NX4 = (MTOT * Ec) / 4;
    const int RB = 256;

    // query -> fp16 once
    cvt_f2h_kernel<<<(NX4 + RB - 1) / RB, RB>>>(query, pXh, NX4);

    // Q/K/V projections (weights converted into reused fp16 buffer)
    cvt_f2h_kernel<<<(NW4 + RB - 1) / RB, RB>>>(Wq, pWh, NW4);
    gemm_f16mma<<<ggrid, 256, GSMEM_BYTES>>>(pXh, pWh, nullptr, pQ, MTOT, Ec, Ec, 0.125f, 1);
    cvt_f2h_kernel<<<(NW4 + RB - 1) / RB, RB>>>(Wk, pWh, NW4);
    gemm_f16mma<<<ggrid, 256, GSMEM_BYTES>>>(pXh, pWh, nullptr, pK, MTOT, Ec, Ec, 1.0f, 1);
    cvt_f2h_kernel<<<(NW4 + RB - 1) / RB, RB>>>(Wv, pWh, NW4);
    gemm_f16mma<<<ggrid, 256, GSMEM_BYTES>>>(pXh, pWh, nullptr, pV, MTOT, Ec, Ec, 1.0f, 1);

    lambda_kernel<<<1, 1>>>(lq1, lk1, lq2, lk2);

    flash_f16<<<dim3(Tc / 64, 2 * Hc, Bc), 256, FSMEM_BYTES>>>(pQ, pK, pV, pO);

    combine_kernel<<<Bc * Hc * Tc, 128>>>(pO, gw, pC);

    // output projection (fp32 out)
    cvt_f2h_kernel<<<(NW4 + RB - 1) / RB, RB>>>(Wo, pWh, NW4);
    gemm_f16mma<<<ggrid, 256, GSMEM_BYTES>>>(pC, pWh, out, nullptr, MTOT, Ec, Ec, 1.0f, 0);
}

// round 8
// speedup vs baseline: 6.7311x; 1.0765x over previous
#include <cuda_runtime.h>
#include <cuda_fp16.h>
#include <cstdint>
#include <math.h>

// Problem constants
#define Bc 2
#define Tc 2048
#define Ec 2048
#define Hc 16
#define Dc 64
#define MTOT (Bc * Tc)  // 4096

// ---------------------------------------------------------------------------
// Device scratch (no allocations allowed)
// ---------------------------------------------------------------------------
__device__ __half g_Q[Bc * Tc * Ec];                      // fp16, pre-scaled
__device__ __half g_K[Bc * Tc * Ec];                      // fp16
__device__ __half g_V[Bc * Tc * Ec];                      // fp16
__device__ float  g_O[(size_t)Bc * 2 * Hc * Tc * 2 * Dc]; // [B, 2H, T, 128] fp32
__device__ __half g_ctx[Bc * Tc * Ec];                    // fp16
__device__ __half g_Xh[MTOT * Ec];                        // fp16 query
__device__ __half g_Wh[4 * Ec * Ec];                      // fp16 weights (q,k,v,o)
__device__ float  g_lam;

// ---------------------------------------------------------------------------
// PTX helpers
// ---------------------------------------------------------------------------
__device__ __forceinline__ uint32_t smem_u32(const void* p) {
    uint32_t a;
    asm("{ .reg .u64 t; cvta.to.shared.u64 t, %1; cvt.u32.u64 %0, t; }" : "=r"(a) : "l"(p));
    return a;
}
__device__ __forceinline__ void cpa16(uint32_t saddr, const void* g) {
    asm volatile("cp.async.cg.shared.global [%0], [%1], 16;" :: "r"(saddr), "l"(g));
}
#define CP_COMMIT() asm volatile("cp.async.commit_group;" ::: "memory")
#define CP_WAIT(n) asm volatile("cp.async.wait_group %0;" :: "n"(n) : "memory")

__device__ __forceinline__ void mma_f16(float* d, const uint32_t* a, const uint32_t* b) {
    asm volatile(
        "mma.sync.aligned.m16n8k16.row.col.f32.f16.f16.f32 "
        "{%0,%1,%2,%3}, {%4,%5,%6,%7}, {%8,%9}, {%0,%1,%2,%3};"
        : "+f"(d[0]), "+f"(d[1]), "+f"(d[2]), "+f"(d[3])
        : "r"(a[0]), "r"(a[1]), "r"(a[2]), "r"(a[3]), "r"(b[0]), "r"(b[1]));
}
#define LDSM_X4(r, addr) \
    asm volatile("ldmatrix.sync.aligned.m8n8.x4.shared.b16 {%0,%1,%2,%3}, [%4];" \
                 : "=r"((r)[0]), "=r"((r)[1]), "=r"((r)[2]), "=r"((r)[3]) : "r"(addr))
#define LDSM_X4_T(r, addr) \
    asm volatile("ldmatrix.sync.aligned.m8n8.x4.trans.shared.b16 {%0,%1,%2,%3}, [%4];" \
                 : "=r"((r)[0]), "=r"((r)[1]), "=r"((r)[2]), "=r"((r)[3]) : "r"(addr))

__device__ __forceinline__ uint32_t pack_h2(float lo, float hi) {
    __half2 h = __floats2half2_rn(lo, hi);
    return *(uint32_t*)&h;
}

// ---------------------------------------------------------------------------
// fp32 -> fp16 convert (1:1)
// ---------------------------------------------------------------------------
__global__ __launch_bounds__(256) void cvt_f2h_kernel(
    const float* __restrict__ in, __half* __restrict__ out, int n4)
{
    const int i = blockIdx.x * 256 + threadIdx.x;
    if (i < n4) {
        float4 v = *(const float4*)(in + 4 * (size_t)i);
        __half2* o = (__half2*)(out + 4 * (size_t)i);
        o[0] = __floats2half2_rn(v.x, v.y);
        o[1] = __floats2half2_rn(v.z, v.w);
    }
}

// All four weights in one launch (grid.y selects weight)
__global__ __launch_bounds__(256) void cvt_w4_kernel(
    const float* __restrict__ w0, const float* __restrict__ w1,
    const float* __restrict__ w2, const float* __restrict__ w3,
    __half* __restrict__ out)
{
    const int y = blockIdx.y;
    const float* src = (y == 0) ? w0 : (y == 1) ? w1 : (y == 2) ? w2 : w3;
    const int i = blockIdx.x * 256 + threadIdx.x;
    float4 v = *(const float4*)(src + 4 * (size_t)i);
    __half2* o = (__half2*)(out + (size_t)y * Ec * Ec + 4 * (size_t)i);
    o[0] = __floats2half2_rn(v.x, v.y);
    o[1] = __floats2half2_rn(v.z, v.w);
}

// ---------------------------------------------------------------------------
// FP16 tensor-core GEMM: C[m,n] = alpha * sum_k X[m,k] * W[n,k]  (X @ W^T)
// CTA 128x128, BK=32, 8 warps (2x4), warp 64x32, m16n8k16, fp32 accum.
// ---------------------------------------------------------------------------
#define BM 128
#define BN 128
#define BK 32
#define HLDA 40
#define STAGE_H (BM * HLDA)                      // 5120 halfs per matrix
#define GSMEM_BYTES (3 * 2 * STAGE_H * 2)        // 61440 B

__device__ __forceinline__ void g_stage_load(__half* stage, const __half* __restrict__ X,
                                             const __half* __restrict__ W,
                                             int m0, int n0, int K, int kt, int tid) {
    __half* Ad = stage;
    __half* Bd = stage + STAGE_H;
    const int kcol = kt * BK;
#pragma unroll
    for (int i = 0; i < 2; i++) {
        const int c = tid + 256 * i;
        const int r = c >> 2, sg = c & 3;
        cpa16(smem_u32(Ad + r * HLDA + sg * 8), X + (size_t)(m0 + r) * K + kcol + sg * 8);
        cpa16(smem_u32(Bd + r * HLDA + sg * 8), W + (size_t)(n0 + r) * K + kcol + sg * 8);
    }
    CP_COMMIT();
}

__global__ __launch_bounds__(256) void gemm_f16mma(
    const __half* __restrict__ X, const __half* __restrict__ W,
    float* __restrict__ Cf, __half* __restrict__ Ch,
    int M, int N, int K, float alpha, int out_half)
{
    extern __shared__ __align__(16) __half smem[];
    const int tid = threadIdx.x;
    const int wid = tid >> 5;
    const int lane = tid & 31;
    const int g = lane >> 2;
    const int tig = lane & 3;
    const int warp_m = (wid & 1) * 64;
    const int warp_n = (wid >> 1) * 32;
    const int m0 = blockIdx.y * BM;
    const int n0 = blockIdx.x * BN;
    const int NK = K / BK;

    const uint32_t sb = smem_u32(smem);
    const uint32_t a_off = (uint32_t)(((warp_m + (lane & 15)) * HLDA + (lane >> 4) * 8) * 2);
    const uint32_t b_off = (uint32_t)((STAGE_H + (warp_n + (lane & 7) + ((lane >> 4) << 3)) * HLDA
                                      + ((lane >> 3) & 1) * 8) * 2);

    float acc[4][4][4];
#pragma unroll
    for (int i = 0; i < 4; i++)
#pragma unroll
        for (int j = 0; j < 4; j++)
#pragma unroll
            for (int r = 0; r < 4; r++) acc[i][j][r] = 0.f;

    g_stage_load(smem, X, W, m0, n0, K, 0, tid);
    g_stage_load(smem + 2 * STAGE_H, X, W, m0, n0, K, 1, tid);

    for (int kt = 0; kt < NK; kt++) {
        const int p = kt % 3;
        if (kt + 2 < NK) CP_WAIT(1); else CP_WAIT(0);
        __syncthreads();
        if (kt + 2 < NK)
            g_stage_load(smem + ((kt + 2) % 3) * 2 * STAGE_H, X, W, m0, n0, K, kt + 2, tid);

        const uint32_t stg = sb + (uint32_t)(p * 2 * STAGE_H * 2);
#pragma unroll
        for (int kc = 0; kc < 2; kc++) {
            const uint32_t ko = (uint32_t)(kc * 32);
            uint32_t afr[4][4], b0[4], b1[4];
#pragma unroll
            for (int i = 0; i < 4; i++)
                LDSM_X4(afr[i], stg + a_off + (uint32_t)(i * 16 * HLDA * 2) + ko);
            LDSM_X4(b0, stg + b_off + ko);
            LDSM_X4(b1, stg + b_off + (uint32_t)(16 * HLDA * 2) + ko);
            uint32_t bfr[4][2];
            bfr[0][0] = b0[0]; bfr[0][1] = b0[1];
            bfr[1][0] = b0[2]; bfr[1][1] = b0[3];
            bfr[2][0] = b1[0]; bfr[2][1] = b1[1];
            bfr[3][0] = b1[2]; bfr[3][1] = b1[3];
#pragma unroll
            for (int i = 0; i < 4; i++)
#pragma unroll
                for (int j = 0; j < 4; j++)
                    mma_f16(acc[i][j], afr[i], bfr[j]);
        }
    }

#pragma unroll
    for (int i = 0; i < 4; i++) {
#pragma unroll
        for (int j = 0; j < 4; j++) {
            const int row = m0 + warp_m + i * 16 + g;
            const int col = n0 + warp_n + j * 8 + 2 * tig;
            const float c0 = acc[i][j][0] * alpha, c1 = acc[i][j][1] * alpha;
            const float c2 = acc[i][j][2] * alpha, c3 = acc[i][j][3] * alpha;
            if (out_half) {
                *(__half2*)(Ch + (size_t)row * N + col) = __floats2half2_rn(c0, c1);
                *(__half2*)(Ch + (size_t)(row + 8) * N + col) = __floats2half2_rn(c2, c3);
            } else {
                *(float2*)(Cf + (size_t)row * N + col) = make_float2(c0, c1);
                *(float2*)(Cf + (size_t)(row + 8) * N + col) = make_float2(c2, c3);
            }
        }
    }
}

// ---------------------------------------------------------------------------
// Lambda scalar
// ---------------------------------------------------------------------------
__global__ void lambda_kernel(const float* __restrict__ lq1, const float* __restrict__ lk1,
                              const float* __restrict__ lq2, const float* __restrict__ lk2)
{
    float s1 = 0.f, s2 = 0.f;
    for (int i = 0; i < Dc; i++) {
        s1 += lq1[i] * lk1[i];
        s2 += lq2[i] * lk2[i];
    }
    const float LI = 0.8f - 0.6f * expf(-3.6f);
    g_lam = expf(s1) - expf(s2) + LI;
}

// ---------------------------------------------------------------------------
// FP16 flash attention, full-row warp ownership.
// Grid (T/128 [reversed], 2H, B), 256 threads (8 warps).
// Warp w owns Q rows qm0+16w..+15 across ALL 64 key cols -> warp-local softmax,
// P held in registers (S-fragment == next A-fragment). KV double-buffered
// cp.async, ONE barrier per KV tile.
// smem halfs: Qs[128][72] + 2 x (K[64][72] + V[64][136]) = 35840 halfs (71680 B)
// ---------------------------------------------------------------------------
#define FQLD 72
#define FVLD2 136
#define KV_STAGE_H (64 * FQLD + 64 * FVLD2)     // 13312 halfs
#define FSMEM_BYTES ((128 * FQLD + 2 * KV_STAGE_H) * 2)  // 71680 B

__device__ __forceinline__ void f_load_kv(__half* kbuf, const __half* __restrict__ Km,
                                          const __half* __restrict__ Vm,
                                          int brow0, int qoff, int voff, int tid) {
    __half* vbuf = kbuf + 64 * FQLD;
#pragma unroll
    for (int it = 0; it < 2; it++) {
        const int idx = tid + 256 * it;
        const int r = idx >> 3, sg = idx & 7;
        cpa16(smem_u32(kbuf + r * FQLD + sg * 8),
              Km + (size_t)(brow0 + r) * Ec + qoff + sg * 8);
    }
#pragma unroll
    for (int it = 0; it < 4; it++) {
        const int idx = tid + 256 * it;
        const int r = idx >> 4, sg = idx & 15;
        cpa16(smem_u32(vbuf + r * FVLD2 + sg * 8),
              Vm + (size_t)(brow0 + r) * Ec + voff + sg * 8);
    }
    CP_COMMIT();
}

__global__ __launch_bounds__(256) void flash_f16(
    const __half* __restrict__ Q, const __half* __restrict__ Km,
    const __half* __restrict__ Vm, float* __restrict__ O)
{
    extern __shared__ __align__(16) __half smh[];
    __half* Qs = smh;                       // 128*72
    __half* KV0 = Qs + 128 * FQLD;          // stage 0: K then V

    const int qtile = gridDim.x - 1 - blockIdx.x;   // longest CTAs first
    const int h2 = blockIdx.y;
    const int b = blockIdx.z;
    const int tid = threadIdx.x;
    const int wid = tid >> 5;
    const int lane = tid & 31;
    const int g = lane >> 2;
    const int tig = lane & 3;
    const int qm0 = qtile * 128;
    const int qoff = h2 * 64;
    const int voff = (h2 >> 1) * 128;
    const int ntiles = 2 * (qtile + 1);

    // fragment lane offsets (halfs)
    const int a_lrow = lane & 15;
    const int a_lcol = (lane >> 4) * 8;
    const int b_lrow = (lane & 7) + ((lane >> 4) << 3);
    const int b_lcol = ((lane >> 3) & 1) * 8;
    const int v_lrow = (lane & 7) + ((lane >> 3) & 1) * 8;
    const int v_lcol = ((lane >> 4) & 1) * 8;

    // ---- load Q tile ----
#pragma unroll
    for (int it = 0; it < 4; it++) {
        const int idx = tid + 256 * it;
        const int r = idx >> 3, sg = idx & 7;
        *(uint4*)(Qs + r * FQLD + sg * 8) =
            *(const uint4*)(Q + (size_t)(b * Tc + qm0 + r) * Ec + qoff + sg * 8);
    }
    __syncthreads();

    // ---- Q fragments (held all block) ----
    uint32_t qfr[4][4];
    {
        const uint32_t qb = smem_u32(Qs) +
            (uint32_t)(((wid * 16 + a_lrow) * FQLD + a_lcol) * 2);
#pragma unroll
        for (int kd = 0; kd < 4; kd++)
            LDSM_X4(qfr[kd], qb + (uint32_t)(kd * 32));
    }

    float oacc[16][4];
#pragma unroll
    for (int j = 0; j < 16; j++)
#pragma unroll
        for (int r = 0; r < 4; r++) oacc[j][r] = 0.f;
    float mrow0 = -1e30f, mrow1 = -1e30f;
    float lrow0 = 0.f, lrow1 = 0.f;
    const int rowa = qm0 + wid * 16 + g;   // this thread's rows: rowa, rowa+8

    // prologue KV load
    f_load_kv(KV0, Km, Vm, b * Tc, qoff, voff, tid);

    for (int kt = 0; kt < ntiles; kt++) {
        CP_WAIT(0);
        __syncthreads();
        if (kt + 1 < ntiles)
            f_load_kv(KV0 + ((kt + 1) & 1) * KV_STAGE_H, Km, Vm,
                      b * Tc + (kt + 1) * 64, qoff, voff, tid);

        const __half* Kbuf = KV0 + (kt & 1) * KV_STAGE_H;
        const __half* Vbuf = Kbuf + 64 * FQLD;
        const uint32_t ksb = smem_u32(Kbuf) + (uint32_t)((b_lrow * FQLD + b_lcol) * 2);
        const uint32_t vsb = smem_u32(Vbuf) + (uint32_t)((v_lrow * FVLD2 + v_lcol) * 2);

        // ---- S = Q @ K^T : warp covers all 8 n-atoms ----
        float sacc[8][4];
#pragma unroll
        for (int j = 0; j < 8; j++)
#pragma unroll
            for (int r = 0; r < 4; r++) sacc[j][r] = 0.f;
#pragma unroll
        for (int kd = 0; kd < 4; kd++) {
#pragma unroll
            for (int jp = 0; jp < 4; jp++) {
                uint32_t bl[4];
                LDSM_X4(bl, ksb + (uint32_t)((jp * 16 * FQLD + kd * 16) * 2));
                mma_f16(sacc[2 * jp], qfr[kd], bl);
                mma_f16(sacc[2 * jp + 1], qfr[kd], bl + 2);
            }
        }

        // ---- causal mask ----
        if (kt * 64 + 63 > rowa) {
#pragma unroll
            for (int j = 0; j < 8; j++) {
                const int colb = kt * 64 + j * 8 + 2 * tig;
                if (colb > rowa) sacc[j][0] = -1e30f;
                if (colb + 1 > rowa) sacc[j][1] = -1e30f;
                if (colb > rowa + 8) sacc[j][2] = -1e30f;
                if (colb + 1 > rowa + 8) sacc[j][3] = -1e30f;
            }
        }

        // ---- warp-local online softmax (4-lane shfl) ----
        float m0 = -1e30f, m1 = -1e30f;
#pragma unroll
        for (int j = 0; j < 8; j++) {
            m0 = fmaxf(m0, fmaxf(sacc[j][0], sacc[j][1]));
            m1 = fmaxf(m1, fmaxf(sacc[j][2], sacc[j][3]));
        }
#pragma unroll
        for (int off = 1; off <= 2; off <<= 1) {
            m0 = fmaxf(m0, __shfl_xor_sync(0xffffffffu, m0, off));
            m1 = fmaxf(m1, __shfl_xor_sync(0xffffffffu, m1, off));
        }
        const float mn0 = fmaxf(mrow0, m0);
        const float mn1 = fmaxf(mrow1, m1);
        const float al0 = __expf(mrow0 - mn0);
        const float al1 = __expf(mrow1 - mn1);
        mrow0 = mn0; mrow1 = mn1;

        float s0 = 0.f, s1 = 0.f;
#pragma unroll
        for (int j = 0; j < 8; j++) {
            sacc[j][0] = __expf(sacc[j][0] - mn0);
            sacc[j][1] = __expf(sacc[j][1] - mn0);
            sacc[j][2] = __expf(sacc[j][2] - mn1);
            sacc[j][3] = __expf(sacc[j][3] - mn1);
            s0 += sacc[j][0] + sacc[j][1];
            s1 += sacc[j][2] + sacc[j][3];
        }
#pragma unroll
        for (int off = 1; off <= 2; off <<= 1) {
            s0 += __shfl_xor_sync(0xffffffffu, s0, off);
            s1 += __shfl_xor_sync(0xffffffffu, s1, off);
        }
        lrow0 = lrow0 * al0 + s0;
        lrow1 = lrow1 * al1 + s1;
#pragma unroll
        for (int j = 0; j < 16; j++) {
            oacc[j][0] *= al0; oacc[j][1] *= al0;
            oacc[j][2] *= al1; oacc[j][3] *= al1;
        }

        // ---- O += P @ V : P in registers, V via ldmatrix.trans ----
#pragma unroll
        for (int kn = 0; kn < 4; kn++) {
            uint32_t aP[4];
            aP[0] = pack_h2(sacc[2 * kn][0], sacc[2 * kn][1]);
            aP[1] = pack_h2(sacc[2 * kn][2], sacc[2 * kn][3]);
            aP[2] = pack_h2(sacc[2 * kn + 1][0], sacc[2 * kn + 1][1]);
            aP[3] = pack_h2(sacc[2 * kn + 1][2], sacc[2 * kn + 1][3]);
#pragma unroll
            for (int jp = 0; jp < 8; jp++) {
                uint32_t vl[4];
                LDSM_X4_T(vl, vsb + (uint32_t)((kn * 16 * FVLD2 + jp * 16) * 2));
                mma_f16(oacc[2 * jp], aP, vl);
                mma_f16(oacc[2 * jp + 1], aP, vl + 2);
            }
        }
    }

    // ---- epilogue ----
    const float inv0 = 1.f / lrow0;
    const float inv1 = 1.f / lrow1;
    float* obase = O + ((size_t)(b * 2 * Hc + h2) * Tc + rowa) * 128;
#pragma unroll
    for (int j = 0; j < 16; j++) {
        const int col = j * 8 + 2 * tig;
        *(float2*)(obase + col) = make_float2(oacc[j][0] * inv0, oacc[j][1] * inv0);
        *(float2*)(obase + 8 * 128 + col) = make_float2(oacc[j][2] * inv1, oacc[j][3] * inv1);
    }
}

// ---------------------------------------------------------------------------
// Combine: warp per row. x = O[2h] - lam*O[2h+1]; RMSNorm(128); * g * (1-LI)
// ---------------------------------------------------------------------------
__global__ __launch_bounds__(256) void combine_kernel(
    const float* __restrict__ O, const float* __restrict__ gw,
    __half* __restrict__ ctx)
{
    const int lane = threadIdx.x & 31;
    const int idx = blockIdx.x * 8 + (threadIdx.x >> 5);   // (b*H + h)*T + t
    const int t = idx % Tc;
    const int h = (idx / Tc) % Hc;
    const int b = idx / (Tc * Hc);

    const size_t base1 = ((size_t)(b * 2 * Hc + 2 * h) * Tc + t) * 128 + lane * 4;
    const size_t base2 = base1 + (size_t)Tc * 128;

    const float lam = g_lam;
    float4 o1 = *(const float4*)(O + base1);
    float4 o2 = *(const float4*)(O + base2);
    float4 x;
    x.x = o1.x - lam * o2.x;
    x.y = o1.y - lam * o2.y;
    x.z = o1.z - lam * o2.z;
    x.w = o1.w - lam * o2.w;

    float v = x.x * x.x + x.y * x.y + x.z * x.z + x.w * x.w;
#pragma unroll
    for (int off = 16; off > 0; off >>= 1)
        v += __shfl_xor_sync(0xffffffffu, v, off);

    const float rms = rsqrtf(v * (1.f / 128.f) + 1e-5f);
    const float LI = 0.8f - 0.6f * expf(-3.6f);
    const float s = rms * (1.f - LI);
    float4 gv = *(const float4*)(gw + lane * 4);

    __half2 h01 = __floats2half2_rn(x.x * s * gv.x, x.y * s * gv.y);
    __half2 h23 = __floats2half2_rn(x.z * s * gv.z, x.w * s * gv.w);
    __half2* dst = (__half2*)(ctx + (size_t)(b * Tc + t) * Ec + h * 128 + lane * 4);
    dst[0] = h01;
    dst[1] = h23;
}

// ---------------------------------------------------------------------------
// Host launcher
// ---------------------------------------------------------------------------
extern "C" void kernel_launch(void* const* d_in, const int* in_sizes, int n_in,
                              void* d_out, int out_size)
{
    (void)in_sizes; (void)n_in; (void)out_size;

    const float* query = (const float*)d_in[0];
    const float* Wq = (const float*)d_in[1];
    const float* Wk = (const float*)d_in[2];
    const float* Wv = (const float*)d_in[3];
    const float* Wo = (const float*)d_in[4];
    const float* lq1 = (const float*)d_in[5];
    const float* lk1 = (const float*)d_in[6];
    const float* lq2 = (const float*)d_in[7];
    const float* lk2 = (const float*)d_in[8];
    const float* gw = (const float*)d_in[9];
    float* out = (float*)d_out;

    __half *pQ, *pK, *pV, *pC, *pXh, *pWh;
    float *pO;
    cudaGetSymbolAddress((void**)&pQ, g_Q);
    cudaGetSymbolAddress((void**)&pK, g_K);
    cudaGetSymbolAddress((void**)&pV, g_V);
    cudaGetSymbolAddress((void**)&pO, g_O);
    cudaGetSymbolAddress((void**)&pC, g_ctx);
    cudaGetSymbolAddress((void**)&pXh, g_Xh);
    cudaGetSymbolAddress((void**)&pWh, g_Wh);

    cudaFuncSetAttribute(gemm_f16mma, cudaFuncAttributeMaxDynamicSharedMemorySize, GSMEM_BYTES);
    cudaFuncSetAttribute(flash_f16, cudaFuncAttributeMaxDynamicSharedMemorySize, FSMEM_BYTES);

    const dim3 ggrid(Ec / 128, MTOT / 128);
    const int NW4 = (Ec * Ec) / 4;
    const int NX4 = (MTOT * Ec) / 4;
    const int RB = 256;

    // conversions up front
    cvt_f2h_kernel<<<(NX4 + RB - 1) / RB, RB>>>(query, pXh, NX4);
    cvt_w4_kernel<<<dim3(NW4 / RB, 4), RB>>>(Wq, Wk, Wv, Wo, pWh);
    lambda_kernel<<<1, 1>>>(lq1, lk1, lq2, lk2);

    // projections
    gemm_f16mma<<<ggrid, 256, GSMEM_BYTES>>>(pXh, pWh + 0 * (size_t)Ec * Ec, nullptr, pQ,
                                             MTOT, Ec, Ec, 0.125f, 1);
    gemm_f16mma<<<ggrid, 256, GSMEM_BYTES>>>(pXh, pWh + 1 * (size_t)Ec * Ec, nullptr, pK,
                                             MTOT, Ec, Ec, 1.0f, 1);
    gemm_f16mma<<<ggrid, 256, GSMEM_BYTES>>>(pXh, pWh + 2 * (size_t)Ec * Ec, nullptr, pV,
                                             MTOT, Ec, Ec, 1.0f, 1);

    flash_f16<<<dim3(Tc / 128, 2 * Hc, Bc), 256, FSMEM_BYTES>>>(pQ, pK, pV, pO);

    combine_kernel<<<Bc * Hc * Tc / 8, 256>>>(pO, gw, pC);

    // output projection (fp32 out)
    gemm_f16mma<<<ggrid, 256, GSMEM_BYTES>>>(pC, pWh + 3 * (size_t)Ec * Ec, out, nullptr,
                                             MTOT, Ec, Ec, 1.0f, 0);
}